// round 5
// baseline (speedup 1.0000x reference)
#include <cuda_runtime.h>
#include <math.h>
#include <stdint.h>

// Problem constants
#define NSEQ 256
#define LRES 384
#define DM   256
#define DP   128
#define NH   8
#define DHD  32
#define HD   256           // NH*DHD
#define NLROWS (NSEQ*LRES) // 98304
#define EPS 1e-5f
#define NWIDE 1280         // 5 fused projection outputs

// -------- scratch (device globals) --------
__device__ uint32_t g_m[NLROWS * DM];        // LN(msa), tf32
__device__ float    g_qsw[LRES * HD];        // q_sw (scaled), fp32
__device__ float    g_ksw[NLROWS * HD];      // k_sw, fp32
__device__ float    g_q[NLROWS * HD];        // m@Wq, fp32
__device__ uint32_t g_qw[NLROWS * HD];       // (q * seq_weight), tf32
__device__ uint32_t g_k[NLROWS * HD];        // m@Wk * scale, tf32
__device__ uint32_t g_v[NLROWS * HD];        // m@Wv, tf32
__device__ float    g_gate[NLROWS * HD];     // sigmoid(m@Wg+bg), fp32
__device__ uint32_t g_aog[NLROWS * HD];      // (attn@v)*gate, tf32
__device__ float    g_sw[NLROWS * NH];       // seq weights
__device__ float    g_logits[NH * LRES * LRES];
__device__ float    g_bias[NH * LRES * LRES];
__device__ uint32_t g_attn[NH * LRES * LRES]; // tf32
__device__ uint32_t g_wpack[DM * NWIDE];      // packed tf32 [k][kSW|Q|K|V|G]
__device__ uint32_t g_w2[2 * DM * DM];        // tf32: qSW, O

// ---- helpers ----
__device__ __forceinline__ uint32_t f2tf(float x) {
    uint32_t u;
    asm("cvt.rna.tf32.f32 %0, %1;" : "=r"(u) : "f"(x));
    return u;
}
__device__ __forceinline__ void mma_tf32(float* c,
    uint32_t a0, uint32_t a1, uint32_t a2, uint32_t a3,
    uint32_t b0, uint32_t b1)
{
    asm volatile(
        "mma.sync.aligned.m16n8k8.row.col.f32.tf32.tf32.f32 "
        "{%0,%1,%2,%3},{%4,%5,%6,%7},{%8,%9},{%0,%1,%2,%3};"
        : "+f"(c[0]), "+f"(c[1]), "+f"(c[2]), "+f"(c[3])
        : "r"(a0), "r"(a1), "r"(a2), "r"(a3), "r"(b0), "r"(b1));
}
__device__ __forceinline__ void cp16(void* s, const void* g) {
    uint32_t sa = (uint32_t)__cvta_generic_to_shared(s);
    asm volatile("cp.async.cg.shared.global [%0], [%1], 16;" :: "r"(sa), "l"(g));
}
#define CP_COMMIT() asm volatile("cp.async.commit_group;")
#define CP_WAIT(n)  asm volatile("cp.async.wait_group %0;" :: "n"(n))

// =========================================================================
// K0a: packed tf32 weight [k][1280]: segs kSW,Q,K,V,G.
// =========================================================================
__global__ void __launch_bounds__(256) cvt_pack_kernel(
    const float* w0, const float* w1, const float* w2, const float* w3,
    const float* w4, uint32_t* dst)
{
    const int idx = blockIdx.x * 256 + threadIdx.x;
    const int k = idx / NWIDE, c = idx % NWIDE;
    const int seg = c >> 8, cc = c & 255;
    const float* src;
    switch (seg) {
        case 0: src = w0; break; case 1: src = w1; break;
        case 2: src = w2; break; case 3: src = w3; break;
        default: src = w4; break;
    }
    dst[idx] = f2tf(src[k * DM + cc]);
}
__global__ void __launch_bounds__(256) cvt2_kernel(
    const float* w0, const float* w1, uint32_t* dst)
{
    const int m = blockIdx.y;
    const int i = blockIdx.x * 256 + threadIdx.x;
    dst[m * (DM * DM) + i] = f2tf(m == 0 ? w0[i] : w1[i]);
}

// =========================================================================
// K1: LayerNorm over msa rows (D=256), writes tf32.
// =========================================================================
__global__ void __launch_bounds__(256) ln_msa_kernel(
    const float* __restrict__ x, const float* __restrict__ g,
    const float* __restrict__ b, uint32_t* __restrict__ out)
{
    const size_t row = blockIdx.x;
    const int t = threadIdx.x;
    float v = x[row * DM + t];
    float s = v, s2 = v * v;
    #pragma unroll
    for (int o = 16; o; o >>= 1) {
        s  += __shfl_xor_sync(0xffffffffu, s,  o);
        s2 += __shfl_xor_sync(0xffffffffu, s2, o);
    }
    __shared__ float ss[8], ss2[8], fin[2];
    const int w = t >> 5, lane = t & 31;
    if (!lane) { ss[w] = s; ss2[w] = s2; }
    __syncthreads();
    if (w == 0) {
        float a  = (lane < 8) ? ss[lane]  : 0.f;
        float a2 = (lane < 8) ? ss2[lane] : 0.f;
        #pragma unroll
        for (int o = 4; o; o >>= 1) {
            a  += __shfl_xor_sync(0xffffffffu, a,  o);
            a2 += __shfl_xor_sync(0xffffffffu, a2, o);
        }
        if (!lane) {
            float mu  = a * (1.f / DM);
            float var = a2 * (1.f / DM) - mu * mu;
            fin[0] = mu; fin[1] = rsqrtf(var + EPS);
        }
    }
    __syncthreads();
    out[row * DM + t] = f2tf((v - fin[0]) * fin[1] * g[t] + b[t]);
}

// =========================================================================
// W1: wide tf32 GEMM. Block 128x128, BK=16, 3-stage cp.async, 1 sync/iter.
// grid: x = N tile (L2 A reuse), y = M tile. 8 warps = 4m x 2n of 32x64.
// MODE 0: fused 5-segment projection epilogue. MODE 1: plain fp32 out.
// =========================================================================
#define WG_LOAD(stg, k0) do {                                                 \
    _Pragma("unroll")                                                         \
    for (int s_ = 0; s_ < 2; s_++) {                                          \
        const int r_ = rA + 64 * s_;                                          \
        cp16(&As[stg][r_][cA * 4], A + (size_t)(m0 + r_) * K + (k0) + cA * 4);\
    }                                                                         \
    _Pragma("unroll")                                                         \
    for (int p_ = 0; p_ < 2; p_++)                                            \
        cp16(&Bs[stg][rB][(cB + 16 * p_) * 4],                                \
             B + (size_t)((k0) + rB) * Nld + n0 + (cB + 16 * p_) * 4);        \
    CP_COMMIT();                                                              \
} while (0)

template<int MODE>
__global__ void __launch_bounds__(256, 2) wgemm_kernel(
    const uint32_t* __restrict__ A, const uint32_t* __restrict__ B,
    int M, int K, int Nld,
    float* __restrict__ ksw, float* __restrict__ qf,
    uint32_t* __restrict__ ktf, uint32_t* __restrict__ vtf,
    float* __restrict__ gatef,
    const float* __restrict__ bias0, const float* __restrict__ bias1,
    float scaleArg, float* __restrict__ C)
{
    extern __shared__ uint32_t dyn[];
    uint32_t (*As)[128][20] = (uint32_t (*)[128][20])dyn;
    uint32_t (*Bs)[16][136] = (uint32_t (*)[16][136])(dyn + 3 * 128 * 20);
    const int tid = threadIdx.x;
    const int n0 = blockIdx.x * 128;
    const int m0 = blockIdx.y * 128;
    const int lane = tid & 31, w = tid >> 5;
    const int wm = w >> 1, wn = w & 1;
    const int gid = lane >> 2, tig = lane & 3;
    const int rA = tid >> 2, cA = tid & 3;
    const int rB = tid >> 4, cB = tid & 15;
    float acc[2][8][4] = {};

    const int T = K >> 4;
    WG_LOAD(0, 0);
    WG_LOAD(1, 16);
    int st = 0, ld = 2;
    for (int t = 0; t < T; t++) {
        if (t + 1 < T) { CP_WAIT(1); } else { CP_WAIT(0); }
        __syncthreads();
        if (t + 2 < T) {
            WG_LOAD(ld, (t + 2) << 4);
            ld = (ld == 2) ? 0 : ld + 1;
        }
        #pragma unroll
        for (int ks = 0; ks < 2; ks++) {
            const int kb = ks * 8;
            uint32_t a[2][4], bfr[8][2];
            #pragma unroll
            for (int mt = 0; mt < 2; mt++) {
                const int rm = wm * 32 + mt * 16 + gid;
                a[mt][0] = As[st][rm    ][kb + tig];
                a[mt][1] = As[st][rm + 8][kb + tig];
                a[mt][2] = As[st][rm    ][kb + tig + 4];
                a[mt][3] = As[st][rm + 8][kb + tig + 4];
            }
            #pragma unroll
            for (int nt = 0; nt < 8; nt++) {
                const int nc = wn * 64 + nt * 8 + gid;
                bfr[nt][0] = Bs[st][kb + tig    ][nc];
                bfr[nt][1] = Bs[st][kb + tig + 4][nc];
            }
            #pragma unroll
            for (int mt = 0; mt < 2; mt++)
                #pragma unroll
                for (int nt = 0; nt < 8; nt++)
                    mma_tf32(acc[mt][nt], a[mt][0], a[mt][1], a[mt][2], a[mt][3],
                             bfr[nt][0], bfr[nt][1]);
        }
        st = (st == 2) ? 0 : st + 1;
    }
    // epilogue
    const int seg = (MODE == 0) ? (blockIdx.x >> 1) : 0;
    #pragma unroll
    for (int mt = 0; mt < 2; mt++) {
        const int r0 = m0 + wm * 32 + mt * 16 + gid;
        #pragma unroll
        for (int nt = 0; nt < 8; nt++) {
            const int col = n0 + wn * 64 + nt * 8 + 2 * tig;
            float v00 = acc[mt][nt][0], v01 = acc[mt][nt][1];
            float v10 = acc[mt][nt][2], v11 = acc[mt][nt][3];
            if (MODE == 0) {
                const int cc = col & 255;
                const size_t p0 = (size_t)r0 * HD + cc;
                const size_t p1 = (size_t)(r0 + 8) * HD + cc;
                switch (seg) {
                    case 0: {
                        const float b0 = bias0[cc], b1 = bias0[cc + 1];
                        *(float2*)(ksw + p0) = make_float2(v00 + b0, v01 + b1);
                        *(float2*)(ksw + p1) = make_float2(v10 + b0, v11 + b1);
                        break;
                    }
                    case 1: {
                        *(float2*)(qf + p0) = make_float2(v00, v01);
                        *(float2*)(qf + p1) = make_float2(v10, v11);
                        break;
                    }
                    case 2: {
                        *(uint2*)(ktf + p0) = make_uint2(f2tf(v00 * scaleArg), f2tf(v01 * scaleArg));
                        *(uint2*)(ktf + p1) = make_uint2(f2tf(v10 * scaleArg), f2tf(v11 * scaleArg));
                        break;
                    }
                    case 3: {
                        *(uint2*)(vtf + p0) = make_uint2(f2tf(v00), f2tf(v01));
                        *(uint2*)(vtf + p1) = make_uint2(f2tf(v10), f2tf(v11));
                        break;
                    }
                    default: {
                        const float b0 = bias1[cc], b1 = bias1[cc + 1];
                        *(float2*)(gatef + p0) = make_float2(1.f/(1.f+expf(-(v00+b0))),
                                                             1.f/(1.f+expf(-(v01+b1))));
                        *(float2*)(gatef + p1) = make_float2(1.f/(1.f+expf(-(v10+b0))),
                                                             1.f/(1.f+expf(-(v11+b1))));
                        break;
                    }
                }
            } else {
                const float b0 = bias0 ? bias0[col] : 0.f;
                const float b1 = bias0 ? bias0[col + 1] : 0.f;
                *(float2*)(C + (size_t)r0 * Nld + col) =
                    make_float2((v00 + b0) * scaleArg, (v01 + b1) * scaleArg);
                *(float2*)(C + (size_t)(r0 + 8) * Nld + col) =
                    make_float2((v10 + b0) * scaleArg, (v11 + b1) * scaleArg);
            }
        }
    }
}
#undef WG_LOAD

// =========================================================================
// K3: seq-weight softmax over n. grid (L, H).
// =========================================================================
__global__ void __launch_bounds__(256) seqw_kernel(
    const float* __restrict__ qsw, const float* __restrict__ ksw,
    float* __restrict__ sw)
{
    const int i = blockIdx.x, h = blockIdx.y;
    const int t = threadIdx.x;            // = n
    __shared__ __align__(16) float qs[DHD];
    __shared__ float red[8];
    if (t < DHD) qs[t] = qsw[(size_t)i * HD + h * DHD + t];
    __syncthreads();
    const float* kp = ksw + ((size_t)t * LRES + i) * HD + h * DHD;
    float dot = 0.f;
    #pragma unroll
    for (int c = 0; c < 8; c++) {
        float4 k4 = *(const float4*)(kp + 4 * c);
        float4 q4 = *(const float4*)(qs + 4 * c);
        dot += k4.x * q4.x + k4.y * q4.y + k4.z * q4.z + k4.w * q4.w;
    }
    const int w = t >> 5, lane = t & 31;
    float mx = dot;
    #pragma unroll
    for (int o = 16; o; o >>= 1) mx = fmaxf(mx, __shfl_xor_sync(0xffffffffu, mx, o));
    if (!lane) red[w] = mx;
    __syncthreads();
    mx = red[0];
    #pragma unroll
    for (int x = 1; x < 8; x++) mx = fmaxf(mx, red[x]);
    const float e = expf(dot - mx);
    float s = e;
    #pragma unroll
    for (int o = 16; o; o >>= 1) s += __shfl_xor_sync(0xffffffffu, s, o);
    __syncthreads();
    if (!lane) red[w] = s;
    __syncthreads();
    float S = 0.f;
    #pragma unroll
    for (int x = 0; x < 8; x++) S += red[x];
    sw[((size_t)t * LRES + i) * NH + h] = e / S;
}

// =========================================================================
// K3b: qw = tf32(q * seq_weight) elementwise.
// =========================================================================
__global__ void __launch_bounds__(256) qw_kernel(
    const float* __restrict__ q, const float* __restrict__ sw,
    uint32_t* __restrict__ qw)
{
    const size_t i4 = (size_t)blockIdx.x * 256 + threadIdx.x;
    const size_t row = i4 >> 6;
    const int h = (int)((i4 >> 3) & 7);
    const float s = sw[row * NH + h];
    float4 v = *(const float4*)(q + i4 * 4);
    uint4 o;
    o.x = f2tf(v.x * s); o.y = f2tf(v.y * s);
    o.z = f2tf(v.z * s); o.w = f2tf(v.w * s);
    *(uint4*)(qw + i4 * 4) = o;
}

// =========================================================================
// T2: logits. Block 64x64, BK=32 (one n/step), 3-stage. grid (6,6,8).
// =========================================================================
#define LG_LOAD(stg, n) do {                                                        \
    const size_t bi_ = (size_t)(n) * LRES;                                          \
    _Pragma("unroll")                                                               \
    for (int s_ = 0; s_ < 2; s_++) {                                                \
        const int r_ = rL + 32 * s_;                                                \
        cp16(&As[stg][r_][cL * 4], qw + (bi_ + i0 + r_) * HD + h * DHD + cL * 4);   \
        cp16(&Bs[stg][r_][cL * 4], kk + (bi_ + j0 + r_) * HD + h * DHD + cL * 4);   \
    }                                                                               \
    CP_COMMIT();                                                                    \
} while (0)

__global__ void __launch_bounds__(256, 2) logits_tc_kernel(
    const uint32_t* __restrict__ qw, const uint32_t* __restrict__ kk,
    float* __restrict__ out)
{
    extern __shared__ uint32_t dyn[];
    uint32_t (*As)[64][36] = (uint32_t (*)[64][36])dyn;
    uint32_t (*Bs)[64][36] = (uint32_t (*)[64][36])(dyn + 3 * 64 * 36);
    const int tid = threadIdx.x;
    const int i0 = blockIdx.x * 64;
    const int j0 = blockIdx.y * 64;
    const int h  = blockIdx.z;
    const int lane = tid & 31, w = tid >> 5;
    const int wm = w >> 1, wn = w & 1;
    const int gid = lane >> 2, tig = lane & 3;
    const int rL = tid >> 3, cL = tid & 7;
    float acc[4][4] = {};

    LG_LOAD(0, 0);
    LG_LOAD(1, 1);
    int st = 0, ld = 2;
    for (int n = 0; n < NSEQ; n++) {
        if (n + 1 < NSEQ) { CP_WAIT(1); } else { CP_WAIT(0); }
        __syncthreads();
        if (n + 2 < NSEQ) {
            LG_LOAD(ld, n + 2);
            ld = (ld == 2) ? 0 : ld + 1;
        }
        #pragma unroll
        for (int ks = 0; ks < 4; ks++) {
            const int kb = ks * 8;
            const int rm = wm * 16 + gid;
            const uint32_t a0 = As[st][rm    ][kb + tig];
            const uint32_t a1 = As[st][rm + 8][kb + tig];
            const uint32_t a2 = As[st][rm    ][kb + tig + 4];
            const uint32_t a3 = As[st][rm + 8][kb + tig + 4];
            #pragma unroll
            for (int nt = 0; nt < 4; nt++) {
                const int nc = wn * 32 + nt * 8 + gid;
                mma_tf32(acc[nt], a0, a1, a2, a3,
                         Bs[st][nc][kb + tig], Bs[st][nc][kb + tig + 4]);
            }
        }
        st = (st == 2) ? 0 : st + 1;
    }
    const size_t ob = (size_t)h * LRES * LRES;
    const int r0 = i0 + wm * 16 + gid;
    #pragma unroll
    for (int nt = 0; nt < 4; nt++) {
        const int col = j0 + wn * 32 + nt * 8 + 2 * tig;
        *(float2*)(out + ob + (size_t)r0 * LRES + col)     = make_float2(acc[nt][0], acc[nt][1]);
        *(float2*)(out + ob + (size_t)(r0+8) * LRES + col) = make_float2(acc[nt][2], acc[nt][3]);
    }
}
#undef LG_LOAD

// =========================================================================
// K5: pair bias. One warp per (i,j).
// =========================================================================
__global__ void __launch_bounds__(256) pairbias_kernel(
    const float* __restrict__ pair, const float* __restrict__ g,
    const float* __restrict__ b, const float* __restrict__ Wb,
    float* __restrict__ bias)
{
    const int w = threadIdx.x >> 5, lane = threadIdx.x & 31;
    const size_t p = (size_t)blockIdx.x * 8 + w;
    float4 v = *(const float4*)(pair + p * DP + lane * 4);
    float s  = v.x + v.y + v.z + v.w;
    float s2 = v.x * v.x + v.y * v.y + v.z * v.z + v.w * v.w;
    #pragma unroll
    for (int o = 16; o; o >>= 1) {
        s  += __shfl_xor_sync(0xffffffffu, s,  o);
        s2 += __shfl_xor_sync(0xffffffffu, s2, o);
    }
    const float mu   = s * (1.f / DP);
    const float rstd = rsqrtf(s2 * (1.f / DP) - mu * mu + EPS);
    float xv[4] = {v.x, v.y, v.z, v.w};
    float acc[8] = {};
    #pragma unroll
    for (int c = 0; c < 4; c++) {
        const int d = lane * 4 + c;
        const float y = (xv[c] - mu) * rstd * g[d] + b[d];
        const float* wr = Wb + d * NH;
        #pragma unroll
        for (int hh = 0; hh < 8; hh++) acc[hh] = fmaf(y, wr[hh], acc[hh]);
    }
    #pragma unroll
    for (int hh = 0; hh < 8; hh++) {
        float a = acc[hh];
        #pragma unroll
        for (int o = 16; o; o >>= 1) a += __shfl_xor_sync(0xffffffffu, a, o);
        if (lane == hh) bias[(size_t)hh * LRES * LRES + p] = a;
    }
}

// =========================================================================
// K6: attn = softmax_j(logits + bias), tf32 output. grid (L, H), 128 thr.
// =========================================================================
__global__ void __launch_bounds__(128) rowsoftmax_kernel(
    const float* __restrict__ logits, const float* __restrict__ bias,
    uint32_t* __restrict__ attn)
{
    const int i = blockIdx.x, h = blockIdx.y;
    const size_t base = ((size_t)h * LRES + i) * LRES;
    const int t = threadIdx.x;
    __shared__ float red[4];
    float x[3];
    #pragma unroll
    for (int r = 0; r < 3; r++) {
        const int j = t + r * 128;
        x[r] = logits[base + j] + bias[base + j];
    }
    float mx = fmaxf(fmaxf(x[0], x[1]), x[2]);
    #pragma unroll
    for (int o = 16; o; o >>= 1) mx = fmaxf(mx, __shfl_xor_sync(0xffffffffu, mx, o));
    const int w = t >> 5, lane = t & 31;
    if (!lane) red[w] = mx;
    __syncthreads();
    mx = fmaxf(fmaxf(red[0], red[1]), fmaxf(red[2], red[3]));
    float e[3], sum = 0.f;
    #pragma unroll
    for (int r = 0; r < 3; r++) { e[r] = expf(x[r] - mx); sum += e[r]; }
    #pragma unroll
    for (int o = 16; o; o >>= 1) sum += __shfl_xor_sync(0xffffffffu, sum, o);
    __syncthreads();
    if (!lane) red[w] = sum;
    __syncthreads();
    const float inv = 1.f / (red[0] + red[1] + red[2] + red[3]);
    #pragma unroll
    for (int r = 0; r < 3; r++) attn[base + t + r * 128] = f2tf(e[r] * inv);
}

// =========================================================================
// T3: aog = tf32(gate * (attn @ v)). Block 128(i)x64(nd), BK=16, 3-stage.
// grid (3, 128, 8).
// =========================================================================
#define AO_LOAD(stg, j0) do {                                                      \
    _Pragma("unroll")                                                              \
    for (int s_ = 0; s_ < 2; s_++) {                                               \
        const int r_ = rA + 64 * s_;                                               \
        cp16(&As[stg][r_][cA * 4], Ah + (size_t)(i0 + r_) * LRES + (j0) + cA * 4); \
    }                                                                              \
    cp16(&Bs[stg][rB][cB * 4],                                                     \
         vv + ((size_t)nB * LRES + (j0) + rB) * HD + h * DHD + dB);                \
    CP_COMMIT();                                                                   \
} while (0)

__global__ void __launch_bounds__(256, 2) attnout_tc_kernel(
    const uint32_t* __restrict__ attn, const uint32_t* __restrict__ vv,
    const float* __restrict__ gate, uint32_t* __restrict__ aog)
{
    __shared__ uint32_t As[3][128][20];
    __shared__ uint32_t Bs[3][16][72];
    const int tid = threadIdx.x;
    const int i0 = blockIdx.x * 128;
    const int h  = blockIdx.z;
    const int lane = tid & 31, w = tid >> 5;
    const int wm = w >> 1, wn = w & 1;
    const int gid = lane >> 2, tig = lane & 3;
    const int rA = tid >> 2, cA = tid & 3;
    const int rB = tid >> 4, cB = tid & 15;
    const int nB = (blockIdx.y << 1) + (cB >> 3);
    const int dB = (cB & 7) * 4;
    const uint32_t* Ah = attn + (size_t)h * LRES * LRES;
    float acc[2][4][4] = {};

    const int T = LRES / 16;  // 24
    AO_LOAD(0, 0);
    AO_LOAD(1, 16);
    int st = 0, ld = 2;
    for (int t = 0; t < T; t++) {
        if (t + 1 < T) { CP_WAIT(1); } else { CP_WAIT(0); }
        __syncthreads();
        if (t + 2 < T) {
            AO_LOAD(ld, (t + 2) * 16);
            ld = (ld == 2) ? 0 : ld + 1;
        }
        #pragma unroll
        for (int ks = 0; ks < 2; ks++) {
            const int kb = ks * 8;
            uint32_t a[2][4], bfr[4][2];
            #pragma unroll
            for (int mt = 0; mt < 2; mt++) {
                const int rm = wm * 32 + mt * 16 + gid;
                a[mt][0] = As[st][rm    ][kb + tig];
                a[mt][1] = As[st][rm + 8][kb + tig];
                a[mt][2] = As[st][rm    ][kb + tig + 4];
                a[mt][3] = As[st][rm + 8][kb + tig + 4];
            }
            #pragma unroll
            for (int nt = 0; nt < 4; nt++) {
                const int nc = wn * 32 + nt * 8 + gid;
                bfr[nt][0] = Bs[st][kb + tig    ][nc];
                bfr[nt][1] = Bs[st][kb + tig + 4][nc];
            }
            #pragma unroll
            for (int mt = 0; mt < 2; mt++)
                #pragma unroll
                for (int nt = 0; nt < 4; nt++)
                    mma_tf32(acc[mt][nt], a[mt][0], a[mt][1], a[mt][2], a[mt][3],
                             bfr[nt][0], bfr[nt][1]);
        }
        st = (st == 2) ? 0 : st + 1;
    }
    const int nOut = (blockIdx.y << 1) + wn;
    #pragma unroll
    for (int mt = 0; mt < 2; mt++) {
        const int r0 = i0 + wm * 32 + mt * 16 + gid;
        #pragma unroll
        for (int nt = 0; nt < 4; nt++) {
            const int d = nt * 8 + 2 * tig;
            const size_t p0 = ((size_t)nOut * LRES + r0) * HD + h * DHD + d;
            const size_t p1 = ((size_t)nOut * LRES + r0 + 8) * HD + h * DHD + d;
            const float2 gA = *(const float2*)(gate + p0);
            const float2 gB = *(const float2*)(gate + p1);
            *(uint2*)(aog + p0) = make_uint2(f2tf(acc[mt][nt][0] * gA.x),
                                             f2tf(acc[mt][nt][1] * gA.y));
            *(uint2*)(aog + p1) = make_uint2(f2tf(acc[mt][nt][2] * gB.x),
                                             f2tf(acc[mt][nt][3] * gB.y));
        }
    }
}
#undef AO_LOAD

// =========================================================================
// launcher
// =========================================================================
extern "C" void kernel_launch(void* const* d_in, const int* in_sizes, int n_in,
                              void* d_out, int out_size)
{
    const float* msa       = (const float*)d_in[0];
    const float* pair      = (const float*)d_in[1];
    const float* ln_msa_g  = (const float*)d_in[2];
    const float* ln_msa_b  = (const float*)d_in[3];
    const float* ln_pair_g = (const float*)d_in[4];
    const float* ln_pair_b = (const float*)d_in[5];
    const float* Wq_sw     = (const float*)d_in[6];
    const float* bq_sw     = (const float*)d_in[7];
    const float* Wk_sw     = (const float*)d_in[8];
    const float* bk_sw     = (const float*)d_in[9];
    const float* Wq        = (const float*)d_in[10];
    const float* Wk        = (const float*)d_in[11];
    const float* Wv        = (const float*)d_in[12];
    const float* Wb        = (const float*)d_in[13];
    const float* Wg        = (const float*)d_in[14];
    const float* bg        = (const float*)d_in[15];
    const float* Wo        = (const float*)d_in[16];
    const float* bo        = (const float*)d_in[17];
    float* out = (float*)d_out;

    uint32_t *m_, *qw_, *k_, *v_, *aog_, *attn_, *wpack_, *w2_;
    float *qsw_, *ksw_, *q_, *gate_, *sw_, *logits_, *bias_;
    cudaGetSymbolAddress((void**)&m_,      g_m);
    cudaGetSymbolAddress((void**)&qsw_,    g_qsw);
    cudaGetSymbolAddress((void**)&ksw_,    g_ksw);
    cudaGetSymbolAddress((void**)&q_,      g_q);
    cudaGetSymbolAddress((void**)&qw_,     g_qw);
    cudaGetSymbolAddress((void**)&k_,      g_k);
    cudaGetSymbolAddress((void**)&v_,      g_v);
    cudaGetSymbolAddress((void**)&gate_,   g_gate);
    cudaGetSymbolAddress((void**)&aog_,    g_aog);
    cudaGetSymbolAddress((void**)&sw_,     g_sw);
    cudaGetSymbolAddress((void**)&logits_, g_logits);
    cudaGetSymbolAddress((void**)&bias_,   g_bias);
    cudaGetSymbolAddress((void**)&attn_,   g_attn);
    cudaGetSymbolAddress((void**)&wpack_,  g_wpack);
    cudaGetSymbolAddress((void**)&w2_,     g_w2);

    const float scale = 0.17677669529663687f;  // 1/sqrt(32)
    const uint32_t *WqSW = w2_, *WO = w2_ + DM * DM;

    const int WG_SMEM = (3 * 128 * 20 + 3 * 16 * 136) * 4;   // 56832
    const int LG_SMEM = (3 * 64 * 36 * 2) * 4;               // 55296
    cudaFuncSetAttribute((const void*)wgemm_kernel<0>,
        cudaFuncAttributeMaxDynamicSharedMemorySize, WG_SMEM);
    cudaFuncSetAttribute((const void*)wgemm_kernel<1>,
        cudaFuncAttributeMaxDynamicSharedMemorySize, WG_SMEM);
    cudaFuncSetAttribute((const void*)logits_tc_kernel,
        cudaFuncAttributeMaxDynamicSharedMemorySize, LG_SMEM);

    // preprocessing: pack weights, LN
    cvt_pack_kernel<<<(DM * NWIDE) / 256, 256>>>(Wk_sw, Wq, Wk, Wv, Wg, wpack_);
    cvt2_kernel<<<dim3(DM * DM / 256, 2), 256>>>(Wq_sw, Wo, w2_);
    ln_msa_kernel<<<NLROWS, 256>>>(msa, ln_msa_g, ln_msa_b, m_);

    // fused 5-way projection: grid x = N tiles (A reuse in L2), y = M tiles
    wgemm_kernel<0><<<dim3(NWIDE / 128, NLROWS / 128), 256, WG_SMEM>>>(
        m_, wpack_, NLROWS, DM, NWIDE,
        ksw_, q_, k_, v_, gate_, bk_sw, bg, scale, nullptr);

    // qsw: (m0 @ Wq_sw + bq_sw) * scale
    wgemm_kernel<1><<<dim3(HD / 128, LRES / 128), 256, WG_SMEM>>>(
        m_, WqSW, LRES, DM, HD,
        nullptr, nullptr, nullptr, nullptr, nullptr, bq_sw, nullptr, scale, qsw_);

    // seq weights + weighted q
    seqw_kernel<<<dim3(LRES, NH), 256>>>(qsw_, ksw_, sw_);
    qw_kernel<<<(NLROWS * HD / 4) / 256, 256>>>(q_, sw_, qw_);

    // logits
    logits_tc_kernel<<<dim3(LRES / 64, LRES / 64, NH), 256, LG_SMEM>>>(qw_, k_, logits_);

    // pair bias + softmax
    pairbias_kernel<<<(LRES * LRES) / 8, 256>>>(pair, ln_pair_g, ln_pair_b, Wb, bias_);
    rowsoftmax_kernel<<<dim3(LRES, NH), 128>>>(logits_, bias_, attn_);

    // attn @ v (gate fused)
    attnout_tc_kernel<<<dim3(LRES / 128, (NSEQ * DHD) / 64, NH), 256>>>(attn_, v_, gate_, aog_);

    // final: aog @ Wo + bo
    wgemm_kernel<1><<<dim3(DM / 128, NLROWS / 128), 256, WG_SMEM>>>(
        aog_, WO, NLROWS, DM, DM,
        nullptr, nullptr, nullptr, nullptr, nullptr, bo, nullptr, 1.f, out);
}

// round 6
// speedup vs baseline: 1.4564x; 1.4564x over previous
#include <cuda_runtime.h>
#include <math.h>
#include <stdint.h>

// Problem constants
#define NSEQ 256
#define LRES 384
#define DM   256
#define DP   128
#define NH   8
#define DHD  32
#define HD   256           // NH*DHD
#define NLROWS (NSEQ*LRES) // 98304
#define EPS 1e-5f
#define NWIDE 1280         // 5 fused projection outputs

// -------- scratch (device globals) --------
__device__ uint32_t g_m[NLROWS * DM];        // LN(msa), tf32
__device__ float    g_qsw[LRES * HD];        // q_sw (scaled), fp32
__device__ float    g_ksw[NLROWS * HD];      // k_sw, fp32
__device__ float    g_q[NLROWS * HD];        // m@Wq, fp32
__device__ uint32_t g_qw[NLROWS * HD];       // (q * seq_weight), tf32
__device__ uint32_t g_k[NLROWS * HD];        // m@Wk * scale, tf32
__device__ uint32_t g_v[NLROWS * HD];        // m@Wv, tf32
__device__ float    g_gate[NLROWS * HD];     // sigmoid(m@Wg+bg), fp32
__device__ uint32_t g_aog[NLROWS * HD];      // (attn@v)*gate, tf32
__device__ float    g_sw[NLROWS * NH];       // seq weights
__device__ float    g_logits[NH * LRES * LRES];
__device__ uint32_t g_attn[NH * LRES * LRES]; // tf32
__device__ uint32_t g_wpack[DM * NWIDE];      // packed tf32 [k][kSW|Q|K|V|G]
__device__ uint32_t g_w2[2 * DM * DM];        // tf32: qSW, O

// ---- helpers ----
__device__ __forceinline__ uint32_t f2tf(float x) {
    uint32_t u;
    asm("cvt.rna.tf32.f32 %0, %1;" : "=r"(u) : "f"(x));
    return u;
}
__device__ __forceinline__ void mma_tf32(float* c,
    uint32_t a0, uint32_t a1, uint32_t a2, uint32_t a3,
    uint32_t b0, uint32_t b1)
{
    asm volatile(
        "mma.sync.aligned.m16n8k8.row.col.f32.tf32.tf32.f32 "
        "{%0,%1,%2,%3},{%4,%5,%6,%7},{%8,%9},{%0,%1,%2,%3};"
        : "+f"(c[0]), "+f"(c[1]), "+f"(c[2]), "+f"(c[3])
        : "r"(a0), "r"(a1), "r"(a2), "r"(a3), "r"(b0), "r"(b1));
}
__device__ __forceinline__ void cp16(void* s, const void* g) {
    uint32_t sa = (uint32_t)__cvta_generic_to_shared(s);
    asm volatile("cp.async.cg.shared.global [%0], [%1], 16;" :: "r"(sa), "l"(g));
}
#define CP_COMMIT() asm volatile("cp.async.commit_group;")
#define CP_WAIT(n)  asm volatile("cp.async.wait_group %0;" :: "n"(n))

// =========================================================================
// K0a: packed tf32 weight [k][1280]: segs kSW,Q,K,V,G.
// =========================================================================
__global__ void __launch_bounds__(256) cvt_pack_kernel(
    const float* w0, const float* w1, const float* w2, const float* w3,
    const float* w4, uint32_t* dst)
{
    const int idx = blockIdx.x * 256 + threadIdx.x;
    const int k = idx / NWIDE, c = idx % NWIDE;
    const int seg = c >> 8, cc = c & 255;
    const float* src;
    switch (seg) {
        case 0: src = w0; break; case 1: src = w1; break;
        case 2: src = w2; break; case 3: src = w3; break;
        default: src = w4; break;
    }
    dst[idx] = f2tf(src[k * DM + cc]);
}
__global__ void __launch_bounds__(256) cvt2_kernel(
    const float* w0, const float* w1, uint32_t* dst)
{
    const int m = blockIdx.y;
    const int i = blockIdx.x * 256 + threadIdx.x;
    dst[m * (DM * DM) + i] = f2tf(m == 0 ? w0[i] : w1[i]);
}

// =========================================================================
// K1: LayerNorm, warp-per-row (D=256), 8 rows/block, writes tf32.
// =========================================================================
__global__ void __launch_bounds__(256) ln_msa_kernel(
    const float* __restrict__ x, const float* __restrict__ g,
    const float* __restrict__ b, uint32_t* __restrict__ out)
{
    const int w = threadIdx.x >> 5, lane = threadIdx.x & 31;
    const size_t row = (size_t)blockIdx.x * 8 + w;
    const float* xr = x + row * DM;
    float4 v0 = *(const float4*)(xr + lane * 4);
    float4 v1 = *(const float4*)(xr + 128 + lane * 4);
    float s  = v0.x + v0.y + v0.z + v0.w + v1.x + v1.y + v1.z + v1.w;
    float s2 = v0.x*v0.x + v0.y*v0.y + v0.z*v0.z + v0.w*v0.w
             + v1.x*v1.x + v1.y*v1.y + v1.z*v1.z + v1.w*v1.w;
    #pragma unroll
    for (int o = 16; o; o >>= 1) {
        s  += __shfl_xor_sync(0xffffffffu, s,  o);
        s2 += __shfl_xor_sync(0xffffffffu, s2, o);
    }
    const float mu   = s * (1.f / DM);
    const float rstd = rsqrtf(s2 * (1.f / DM) - mu * mu + EPS);
    float4 g0 = *(const float4*)(g + lane * 4);
    float4 g1 = *(const float4*)(g + 128 + lane * 4);
    float4 b0 = *(const float4*)(b + lane * 4);
    float4 b1 = *(const float4*)(b + 128 + lane * 4);
    uint4 o0, o1;
    o0.x = f2tf((v0.x - mu) * rstd * g0.x + b0.x);
    o0.y = f2tf((v0.y - mu) * rstd * g0.y + b0.y);
    o0.z = f2tf((v0.z - mu) * rstd * g0.z + b0.z);
    o0.w = f2tf((v0.w - mu) * rstd * g0.w + b0.w);
    o1.x = f2tf((v1.x - mu) * rstd * g1.x + b1.x);
    o1.y = f2tf((v1.y - mu) * rstd * g1.y + b1.y);
    o1.z = f2tf((v1.z - mu) * rstd * g1.z + b1.z);
    o1.w = f2tf((v1.w - mu) * rstd * g1.w + b1.w);
    *(uint4*)(out + row * DM + lane * 4)       = o0;
    *(uint4*)(out + row * DM + 128 + lane * 4) = o1;
}

// =========================================================================
// W1: wide tf32 GEMM. Block 128x128, BK=32, 3-stage cp.async, 1 sync/iter.
// grid: x = N tile, y = M tile. 8 warps = 4m x 2n of 32x64.
// MODE 0: fused 5-segment projection epilogue. MODE 1: plain fp32 out.
// =========================================================================
#define WG_LOAD(stg, k0) do {                                                     \
    _Pragma("unroll")                                                             \
    for (int s_ = 0; s_ < 2; s_++) {                                              \
        const int r_ = rA + 64 * s_;                                              \
        cp16(&As[stg][r_][cA * 4],     A + (size_t)(m0 + r_) * K + (k0) + cA * 4);\
        cp16(&As[stg][r_][(cA+4) * 4], A + (size_t)(m0 + r_) * K + (k0) + (cA+4) * 4);\
    }                                                                             \
    _Pragma("unroll")                                                             \
    for (int p_ = 0; p_ < 4; p_++)                                                \
        cp16(&Bs[stg][rB][(cB + 8 * p_) * 4],                                     \
             B + (size_t)((k0) + rB) * Nld + n0 + (cB + 8 * p_) * 4);             \
    CP_COMMIT();                                                                  \
} while (0)

template<int MODE>
__global__ void __launch_bounds__(256, 2) wgemm_kernel(
    const uint32_t* __restrict__ A, const uint32_t* __restrict__ B,
    int M, int K, int Nld,
    float* __restrict__ ksw, float* __restrict__ qf,
    uint32_t* __restrict__ ktf, uint32_t* __restrict__ vtf,
    float* __restrict__ gatef,
    const float* __restrict__ bias0, const float* __restrict__ bias1,
    float scaleArg, float* __restrict__ C)
{
    extern __shared__ uint32_t dyn[];
    uint32_t (*As)[128][36] = (uint32_t (*)[128][36])dyn;
    uint32_t (*Bs)[32][136] = (uint32_t (*)[32][136])(dyn + 3 * 128 * 36);
    const int tid = threadIdx.x;
    const int n0 = blockIdx.x * 128;
    const int m0 = blockIdx.y * 128;
    const int lane = tid & 31, w = tid >> 5;
    const int wm = w >> 1, wn = w & 1;
    const int gid = lane >> 2, tig = lane & 3;
    const int rA = tid >> 2, cA = tid & 3;    // A: rows rA, rA+64; f4 cols cA, cA+4
    const int rB = tid >> 3, cB = tid & 7;    // B: k-row rB (0..31), f4 cols cB+8p
    float acc[2][8][4] = {};

    const int T = K >> 5;   // BK=32
    WG_LOAD(0, 0);
    WG_LOAD(1, 32);
    int st = 0, ld = 2;
    for (int t = 0; t < T; t++) {
        if (t + 1 < T) { CP_WAIT(1); } else { CP_WAIT(0); }
        __syncthreads();
        if (t + 2 < T) {
            WG_LOAD(ld, (t + 2) << 5);
            ld = (ld == 2) ? 0 : ld + 1;
        }
        #pragma unroll
        for (int ks = 0; ks < 4; ks++) {
            const int kb = ks * 8;
            uint32_t a[2][4], bfr[8][2];
            #pragma unroll
            for (int mt = 0; mt < 2; mt++) {
                const int rm = wm * 32 + mt * 16 + gid;
                a[mt][0] = As[st][rm    ][kb + tig];
                a[mt][1] = As[st][rm + 8][kb + tig];
                a[mt][2] = As[st][rm    ][kb + tig + 4];
                a[mt][3] = As[st][rm + 8][kb + tig + 4];
            }
            #pragma unroll
            for (int nt = 0; nt < 8; nt++) {
                const int nc = wn * 64 + nt * 8 + gid;
                bfr[nt][0] = Bs[st][kb + tig    ][nc];
                bfr[nt][1] = Bs[st][kb + tig + 4][nc];
            }
            #pragma unroll
            for (int mt = 0; mt < 2; mt++)
                #pragma unroll
                for (int nt = 0; nt < 8; nt++)
                    mma_tf32(acc[mt][nt], a[mt][0], a[mt][1], a[mt][2], a[mt][3],
                             bfr[nt][0], bfr[nt][1]);
        }
        st = (st == 2) ? 0 : st + 1;
    }
    // epilogue
    const int seg = (MODE == 0) ? (blockIdx.x >> 1) : 0;
    #pragma unroll
    for (int mt = 0; mt < 2; mt++) {
        const int r0 = m0 + wm * 32 + mt * 16 + gid;
        #pragma unroll
        for (int nt = 0; nt < 8; nt++) {
            const int col = n0 + wn * 64 + nt * 8 + 2 * tig;
            float v00 = acc[mt][nt][0], v01 = acc[mt][nt][1];
            float v10 = acc[mt][nt][2], v11 = acc[mt][nt][3];
            if (MODE == 0) {
                const int cc = col & 255;
                const size_t p0 = (size_t)r0 * HD + cc;
                const size_t p1 = (size_t)(r0 + 8) * HD + cc;
                switch (seg) {
                    case 0: {
                        const float b0 = bias0[cc], b1 = bias0[cc + 1];
                        *(float2*)(ksw + p0) = make_float2(v00 + b0, v01 + b1);
                        *(float2*)(ksw + p1) = make_float2(v10 + b0, v11 + b1);
                        break;
                    }
                    case 1: {
                        *(float2*)(qf + p0) = make_float2(v00, v01);
                        *(float2*)(qf + p1) = make_float2(v10, v11);
                        break;
                    }
                    case 2: {
                        *(uint2*)(ktf + p0) = make_uint2(f2tf(v00 * scaleArg), f2tf(v01 * scaleArg));
                        *(uint2*)(ktf + p1) = make_uint2(f2tf(v10 * scaleArg), f2tf(v11 * scaleArg));
                        break;
                    }
                    case 3: {
                        *(uint2*)(vtf + p0) = make_uint2(f2tf(v00), f2tf(v01));
                        *(uint2*)(vtf + p1) = make_uint2(f2tf(v10), f2tf(v11));
                        break;
                    }
                    default: {
                        const float b0 = bias1[cc], b1 = bias1[cc + 1];
                        *(float2*)(gatef + p0) = make_float2(1.f/(1.f+expf(-(v00+b0))),
                                                             1.f/(1.f+expf(-(v01+b1))));
                        *(float2*)(gatef + p1) = make_float2(1.f/(1.f+expf(-(v10+b0))),
                                                             1.f/(1.f+expf(-(v11+b1))));
                        break;
                    }
                }
            } else {
                const float b0 = bias0 ? bias0[col] : 0.f;
                const float b1 = bias0 ? bias0[col + 1] : 0.f;
                *(float2*)(C + (size_t)r0 * Nld + col) =
                    make_float2((v00 + b0) * scaleArg, (v01 + b1) * scaleArg);
                *(float2*)(C + (size_t)(r0 + 8) * Nld + col) =
                    make_float2((v10 + b0) * scaleArg, (v11 + b1) * scaleArg);
            }
        }
    }
}
#undef WG_LOAD

// =========================================================================
// K3: seq-weight softmax over n. grid (L, H).
// =========================================================================
__global__ void __launch_bounds__(256) seqw_kernel(
    const float* __restrict__ qsw, const float* __restrict__ ksw,
    float* __restrict__ sw)
{
    const int i = blockIdx.x, h = blockIdx.y;
    const int t = threadIdx.x;            // = n
    __shared__ __align__(16) float qs[DHD];
    __shared__ float red[8];
    if (t < DHD) qs[t] = qsw[(size_t)i * HD + h * DHD + t];
    __syncthreads();
    const float* kp = ksw + ((size_t)t * LRES + i) * HD + h * DHD;
    float dot = 0.f;
    #pragma unroll
    for (int c = 0; c < 8; c++) {
        float4 k4 = *(const float4*)(kp + 4 * c);
        float4 q4 = *(const float4*)(qs + 4 * c);
        dot += k4.x * q4.x + k4.y * q4.y + k4.z * q4.z + k4.w * q4.w;
    }
    const int w = t >> 5, lane = t & 31;
    float mx = dot;
    #pragma unroll
    for (int o = 16; o; o >>= 1) mx = fmaxf(mx, __shfl_xor_sync(0xffffffffu, mx, o));
    if (!lane) red[w] = mx;
    __syncthreads();
    mx = red[0];
    #pragma unroll
    for (int x = 1; x < 8; x++) mx = fmaxf(mx, red[x]);
    const float e = expf(dot - mx);
    float s = e;
    #pragma unroll
    for (int o = 16; o; o >>= 1) s += __shfl_xor_sync(0xffffffffu, s, o);
    __syncthreads();
    if (!lane) red[w] = s;
    __syncthreads();
    float S = 0.f;
    #pragma unroll
    for (int x = 0; x < 8; x++) S += red[x];
    sw[((size_t)t * LRES + i) * NH + h] = e / S;
}

// =========================================================================
// K3b: qw = tf32(q * seq_weight) elementwise.
// =========================================================================
__global__ void __launch_bounds__(256) qw_kernel(
    const float* __restrict__ q, const float* __restrict__ sw,
    uint32_t* __restrict__ qw)
{
    const size_t i4 = (size_t)blockIdx.x * 256 + threadIdx.x;
    const size_t row = i4 >> 6;
    const int h = (int)((i4 >> 3) & 7);
    const float s = sw[row * NH + h];
    float4 v = *(const float4*)(q + i4 * 4);
    uint4 o;
    o.x = f2tf(v.x * s); o.y = f2tf(v.y * s);
    o.z = f2tf(v.z * s); o.w = f2tf(v.w * s);
    *(uint4*)(qw + i4 * 4) = o;
}

// =========================================================================
// T2: logits. Block 64x64, BK=64 (two n/step), 3-stage. grid (6,6,8).
// =========================================================================
#define LG_LOAD(stg, np) do {                                                      \
    const int nb_ = (np) * 2;                                                      \
    _Pragma("unroll")                                                              \
    for (int c_ = 0; c_ < 4; c_++) {                                               \
        const int col_ = cL + 4 * c_;                                              \
        const size_t bi_ = (size_t)(nb_ + (col_ >> 3)) * LRES;                     \
        const int dd_ = (col_ & 7) * 4;                                            \
        cp16(&As[stg][rL][col_ * 4], qw + (bi_ + i0 + rL) * HD + h * DHD + dd_);   \
        cp16(&Bs[stg][rL][col_ * 4], kk + (bi_ + j0 + rL) * HD + h * DHD + dd_);   \
    }                                                                              \
    CP_COMMIT();                                                                   \
} while (0)

__global__ void __launch_bounds__(256, 2) logits_tc_kernel(
    const uint32_t* __restrict__ qw, const uint32_t* __restrict__ kk,
    float* __restrict__ out)
{
    extern __shared__ uint32_t dyn[];
    uint32_t (*As)[64][68] = (uint32_t (*)[64][68])dyn;
    uint32_t (*Bs)[64][68] = (uint32_t (*)[64][68])(dyn + 3 * 64 * 68);
    const int tid = threadIdx.x;
    const int i0 = blockIdx.x * 64;
    const int j0 = blockIdx.y * 64;
    const int h  = blockIdx.z;
    const int lane = tid & 31, w = tid >> 5;
    const int wm = w >> 1, wn = w & 1;
    const int gid = lane >> 2, tig = lane & 3;
    const int rL = tid >> 2, cL = tid & 3;
    float acc[4][4] = {};

    const int T = NSEQ / 2;   // 128
    LG_LOAD(0, 0);
    LG_LOAD(1, 1);
    int st = 0, ld = 2;
    for (int t = 0; t < T; t++) {
        if (t + 1 < T) { CP_WAIT(1); } else { CP_WAIT(0); }
        __syncthreads();
        if (t + 2 < T) {
            LG_LOAD(ld, t + 2);
            ld = (ld == 2) ? 0 : ld + 1;
        }
        #pragma unroll
        for (int ks = 0; ks < 8; ks++) {
            const int kb = ks * 8;
            const int rm = wm * 16 + gid;
            const uint32_t a0 = As[st][rm    ][kb + tig];
            const uint32_t a1 = As[st][rm + 8][kb + tig];
            const uint32_t a2 = As[st][rm    ][kb + tig + 4];
            const uint32_t a3 = As[st][rm + 8][kb + tig + 4];
            #pragma unroll
            for (int nt = 0; nt < 4; nt++) {
                const int nc = wn * 32 + nt * 8 + gid;
                mma_tf32(acc[nt], a0, a1, a2, a3,
                         Bs[st][nc][kb + tig], Bs[st][nc][kb + tig + 4]);
            }
        }
        st = (st == 2) ? 0 : st + 1;
    }
    const size_t ob = (size_t)h * LRES * LRES;
    const int r0 = i0 + wm * 16 + gid;
    #pragma unroll
    for (int nt = 0; nt < 4; nt++) {
        const int col = j0 + wn * 32 + nt * 8 + 2 * tig;
        *(float2*)(out + ob + (size_t)r0 * LRES + col)     = make_float2(acc[nt][0], acc[nt][1]);
        *(float2*)(out + ob + (size_t)(r0+8) * LRES + col) = make_float2(acc[nt][2], acc[nt][3]);
    }
}
#undef LG_LOAD

// =========================================================================
// K6: fused pair-bias + softmax. One block per i (256 thr = 8 warps).
// Phase 1: bias_s[j][h] = LN(pair[i,j,:]) @ Wb[:,h]  (warp per j-stride).
// Phase 2: warp h: attn[h][i][:] = tf32(softmax_j(logits + bias_s)).
// =========================================================================
__global__ void __launch_bounds__(256) pairsoftmax_kernel(
    const float* __restrict__ pair, const float* __restrict__ g,
    const float* __restrict__ b, const float* __restrict__ Wb,
    const float* __restrict__ logits, uint32_t* __restrict__ attn)
{
    __shared__ float bias_s[LRES][NH + 1];   // pad 9: conflict-free phase-2 reads
    const int i = blockIdx.x;
    const int w = threadIdx.x >> 5, lane = threadIdx.x & 31;

    for (int j = w; j < LRES; j += 8) {
        const size_t p = (size_t)i * LRES + j;
        float4 v = *(const float4*)(pair + p * DP + lane * 4);
        float s  = v.x + v.y + v.z + v.w;
        float s2 = v.x*v.x + v.y*v.y + v.z*v.z + v.w*v.w;
        #pragma unroll
        for (int o = 16; o; o >>= 1) {
            s  += __shfl_xor_sync(0xffffffffu, s,  o);
            s2 += __shfl_xor_sync(0xffffffffu, s2, o);
        }
        const float mu   = s * (1.f / DP);
        const float rstd = rsqrtf(s2 * (1.f / DP) - mu * mu + EPS);
        float xv[4] = {v.x, v.y, v.z, v.w};
        float acc[8] = {};
        #pragma unroll
        for (int c = 0; c < 4; c++) {
            const int d = lane * 4 + c;
            const float y = (xv[c] - mu) * rstd * g[d] + b[d];
            const float* wr = Wb + d * NH;
            #pragma unroll
            for (int hh = 0; hh < 8; hh++) acc[hh] = fmaf(y, wr[hh], acc[hh]);
        }
        #pragma unroll
        for (int hh = 0; hh < 8; hh++) {
            float a = acc[hh];
            #pragma unroll
            for (int o = 16; o; o >>= 1) a += __shfl_xor_sync(0xffffffffu, a, o);
            if (lane == hh) bias_s[j][hh] = a;
        }
    }
    __syncthreads();

    // phase 2: warp w handles head h = w
    const int h = w;
    const size_t base = ((size_t)h * LRES + i) * LRES;
    float x[12];
    #pragma unroll
    for (int r = 0; r < 12; r++) {
        const int j = lane + 32 * r;
        x[r] = logits[base + j] + bias_s[j][h];
    }
    float mx = x[0];
    #pragma unroll
    for (int r = 1; r < 12; r++) mx = fmaxf(mx, x[r]);
    #pragma unroll
    for (int o = 16; o; o >>= 1) mx = fmaxf(mx, __shfl_xor_sync(0xffffffffu, mx, o));
    float e[12], sum = 0.f;
    #pragma unroll
    for (int r = 0; r < 12; r++) { e[r] = expf(x[r] - mx); sum += e[r]; }
    #pragma unroll
    for (int o = 16; o; o >>= 1) sum += __shfl_xor_sync(0xffffffffu, sum, o);
    const float inv = 1.f / sum;
    #pragma unroll
    for (int r = 0; r < 12; r++) attn[base + lane + 32 * r] = f2tf(e[r] * inv);
}

// =========================================================================
// T3: aog = tf32(gate * (attn @ v)). Block 128(i)x64(nd), BK=16, 3-stage.
// grid (3, 128, 8).
// =========================================================================
#define AO_LOAD(stg, j0) do {                                                      \
    _Pragma("unroll")                                                              \
    for (int s_ = 0; s_ < 2; s_++) {                                               \
        const int r_ = rA + 64 * s_;                                               \
        cp16(&As[stg][r_][cA * 4], Ah + (size_t)(i0 + r_) * LRES + (j0) + cA * 4); \
    }                                                                              \
    cp16(&Bs[stg][rB][cB * 4],                                                     \
         vv + ((size_t)nB * LRES + (j0) + rB) * HD + h * DHD + dB);                \
    CP_COMMIT();                                                                   \
} while (0)

__global__ void __launch_bounds__(256, 2) attnout_tc_kernel(
    const uint32_t* __restrict__ attn, const uint32_t* __restrict__ vv,
    const float* __restrict__ gate, uint32_t* __restrict__ aog)
{
    __shared__ uint32_t As[3][128][20];
    __shared__ uint32_t Bs[3][16][72];
    const int tid = threadIdx.x;
    const int i0 = blockIdx.x * 128;
    const int h  = blockIdx.z;
    const int lane = tid & 31, w = tid >> 5;
    const int wm = w >> 1, wn = w & 1;
    const int gid = lane >> 2, tig = lane & 3;
    const int rA = tid >> 2, cA = tid & 3;
    const int rB = tid >> 4, cB = tid & 15;
    const int nB = (blockIdx.y << 1) + (cB >> 3);
    const int dB = (cB & 7) * 4;
    const uint32_t* Ah = attn + (size_t)h * LRES * LRES;
    float acc[2][4][4] = {};

    const int T = LRES / 16;  // 24
    AO_LOAD(0, 0);
    AO_LOAD(1, 16);
    int st = 0, ld = 2;
    for (int t = 0; t < T; t++) {
        if (t + 1 < T) { CP_WAIT(1); } else { CP_WAIT(0); }
        __syncthreads();
        if (t + 2 < T) {
            AO_LOAD(ld, (t + 2) * 16);
            ld = (ld == 2) ? 0 : ld + 1;
        }
        #pragma unroll
        for (int ks = 0; ks < 2; ks++) {
            const int kb = ks * 8;
            uint32_t a[2][4], bfr[4][2];
            #pragma unroll
            for (int mt = 0; mt < 2; mt++) {
                const int rm = wm * 32 + mt * 16 + gid;
                a[mt][0] = As[st][rm    ][kb + tig];
                a[mt][1] = As[st][rm + 8][kb + tig];
                a[mt][2] = As[st][rm    ][kb + tig + 4];
                a[mt][3] = As[st][rm + 8][kb + tig + 4];
            }
            #pragma unroll
            for (int nt = 0; nt < 4; nt++) {
                const int nc = wn * 32 + nt * 8 + gid;
                bfr[nt][0] = Bs[st][kb + tig    ][nc];
                bfr[nt][1] = Bs[st][kb + tig + 4][nc];
            }
            #pragma unroll
            for (int mt = 0; mt < 2; mt++)
                #pragma unroll
                for (int nt = 0; nt < 4; nt++)
                    mma_tf32(acc[mt][nt], a[mt][0], a[mt][1], a[mt][2], a[mt][3],
                             bfr[nt][0], bfr[nt][1]);
        }
        st = (st == 2) ? 0 : st + 1;
    }
    const int nOut = (blockIdx.y << 1) + wn;
    #pragma unroll
    for (int mt = 0; mt < 2; mt++) {
        const int r0 = i0 + wm * 32 + mt * 16 + gid;
        #pragma unroll
        for (int nt = 0; nt < 4; nt++) {
            const int d = nt * 8 + 2 * tig;
            const size_t p0 = ((size_t)nOut * LRES + r0) * HD + h * DHD + d;
            const size_t p1 = ((size_t)nOut * LRES + r0 + 8) * HD + h * DHD + d;
            const float2 gA = *(const float2*)(gate + p0);
            const float2 gB = *(const float2*)(gate + p1);
            *(uint2*)(aog + p0) = make_uint2(f2tf(acc[mt][nt][0] * gA.x),
                                             f2tf(acc[mt][nt][1] * gA.y));
            *(uint2*)(aog + p1) = make_uint2(f2tf(acc[mt][nt][2] * gB.x),
                                             f2tf(acc[mt][nt][3] * gB.y));
        }
    }
}
#undef AO_LOAD

// =========================================================================
// launcher
// =========================================================================
extern "C" void kernel_launch(void* const* d_in, const int* in_sizes, int n_in,
                              void* d_out, int out_size)
{
    const float* msa       = (const float*)d_in[0];
    const float* pair      = (const float*)d_in[1];
    const float* ln_msa_g  = (const float*)d_in[2];
    const float* ln_msa_b  = (const float*)d_in[3];
    const float* ln_pair_g = (const float*)d_in[4];
    const float* ln_pair_b = (const float*)d_in[5];
    const float* Wq_sw     = (const float*)d_in[6];
    const float* bq_sw     = (const float*)d_in[7];
    const float* Wk_sw     = (const float*)d_in[8];
    const float* bk_sw     = (const float*)d_in[9];
    const float* Wq        = (const float*)d_in[10];
    const float* Wk        = (const float*)d_in[11];
    const float* Wv        = (const float*)d_in[12];
    const float* Wb        = (const float*)d_in[13];
    const float* Wg        = (const float*)d_in[14];
    const float* bg        = (const float*)d_in[15];
    const float* Wo        = (const float*)d_in[16];
    const float* bo        = (const float*)d_in[17];
    float* out = (float*)d_out;

    uint32_t *m_, *qw_, *k_, *v_, *aog_, *attn_, *wpack_, *w2_;
    float *qsw_, *ksw_, *q_, *gate_, *sw_, *logits_;
    cudaGetSymbolAddress((void**)&m_,      g_m);
    cudaGetSymbolAddress((void**)&qsw_,    g_qsw);
    cudaGetSymbolAddress((void**)&ksw_,    g_ksw);
    cudaGetSymbolAddress((void**)&q_,      g_q);
    cudaGetSymbolAddress((void**)&qw_,     g_qw);
    cudaGetSymbolAddress((void**)&k_,      g_k);
    cudaGetSymbolAddress((void**)&v_,      g_v);
    cudaGetSymbolAddress((void**)&gate_,   g_gate);
    cudaGetSymbolAddress((void**)&aog_,    g_aog);
    cudaGetSymbolAddress((void**)&sw_,     g_sw);
    cudaGetSymbolAddress((void**)&logits_, g_logits);
    cudaGetSymbolAddress((void**)&attn_,   g_attn);
    cudaGetSymbolAddress((void**)&wpack_,  g_wpack);
    cudaGetSymbolAddress((void**)&w2_,     g_w2);

    const float scale = 0.17677669529663687f;  // 1/sqrt(32)
    const uint32_t *WqSW = w2_, *WO = w2_ + DM * DM;

    const int WG_SMEM = (3 * 128 * 36 + 3 * 32 * 136) * 4;   // 107520
    const int LG_SMEM = (3 * 64 * 68 * 2) * 4;               // 104448
    cudaFuncSetAttribute((const void*)wgemm_kernel<0>,
        cudaFuncAttributeMaxDynamicSharedMemorySize, WG_SMEM);
    cudaFuncSetAttribute((const void*)wgemm_kernel<1>,
        cudaFuncAttributeMaxDynamicSharedMemorySize, WG_SMEM);
    cudaFuncSetAttribute((const void*)logits_tc_kernel,
        cudaFuncAttributeMaxDynamicSharedMemorySize, LG_SMEM);

    // preprocessing: pack weights, LN
    cvt_pack_kernel<<<(DM * NWIDE) / 256, 256>>>(Wk_sw, Wq, Wk, Wv, Wg, wpack_);
    cvt2_kernel<<<dim3(DM * DM / 256, 2), 256>>>(Wq_sw, Wo, w2_);
    ln_msa_kernel<<<NLROWS / 8, 256>>>(msa, ln_msa_g, ln_msa_b, m_);

    // fused 5-way projection
    wgemm_kernel<0><<<dim3(NWIDE / 128, NLROWS / 128), 256, WG_SMEM>>>(
        m_, wpack_, NLROWS, DM, NWIDE,
        ksw_, q_, k_, v_, gate_, bk_sw, bg, scale, nullptr);

    // qsw: (m0 @ Wq_sw + bq_sw) * scale
    wgemm_kernel<1><<<dim3(HD / 128, LRES / 128), 256, WG_SMEM>>>(
        m_, WqSW, LRES, DM, HD,
        nullptr, nullptr, nullptr, nullptr, nullptr, bq_sw, nullptr, scale, qsw_);

    // seq weights + weighted q
    seqw_kernel<<<dim3(LRES, NH), 256>>>(qsw_, ksw_, sw_);
    qw_kernel<<<(NLROWS * HD / 4) / 256, 256>>>(q_, sw_, qw_);

    // logits
    logits_tc_kernel<<<dim3(LRES / 64, LRES / 64, NH), 256, LG_SMEM>>>(qw_, k_, logits_);

    // fused pair bias + softmax
    pairsoftmax_kernel<<<LRES, 256>>>(pair, ln_pair_g, ln_pair_b, Wb, logits_, attn_);

    // attn @ v (gate fused)
    attnout_tc_kernel<<<dim3(LRES / 128, (NSEQ * DHD) / 64, NH), 256>>>(attn_, v_, gate_, aog_);

    // final: aog @ Wo + bo
    wgemm_kernel<1><<<dim3(DM / 128, NLROWS / 128), 256, WG_SMEM>>>(
        aog_, WO, NLROWS, DM, DM,
        nullptr, nullptr, nullptr, nullptr, nullptr, bo, nullptr, 1.f, out);
}

// round 7
// speedup vs baseline: 2.0933x; 1.4373x over previous
#include <cuda_runtime.h>
#include <cuda_fp16.h>
#include <math.h>
#include <stdint.h>

// Problem constants
#define NSEQ 256
#define LRES 384
#define DM   256
#define DP   128
#define NH   8
#define DHD  32
#define HD   256           // NH*DHD
#define NLROWS (NSEQ*LRES) // 98304
#define EPS 1e-5f
#define NWIDE 1280         // 5 fused projection outputs

// -------- scratch (device globals) --------
__device__ __half  g_m[NLROWS * DM];        // LN(msa), fp16
__device__ float   g_qsw[LRES * HD];        // q_sw (scaled), fp32
__device__ float   g_ksw[NLROWS * HD];      // k_sw, fp32
__device__ float   g_q[NLROWS * HD];        // m@Wq, fp32
__device__ __half  g_qw[NLROWS * HD];       // (q * seq_weight), fp16
__device__ __half  g_k[NLROWS * HD];        // m@Wk * scale, fp16
__device__ __half  g_v[NLROWS * HD];        // m@Wv, fp16 [n,j,h,d]
__device__ __half  g_vt[NH * NSEQ * DHD * LRES]; // v^T: [h][n][d][j], fp16
__device__ float   g_gate[NLROWS * HD];     // sigmoid(m@Wg+bg), fp32
__device__ __half  g_aog[NLROWS * HD];      // (attn@v)*gate, fp16
__device__ float   g_sw[NLROWS * NH];       // seq weights
__device__ float   g_logits[NH * LRES * LRES];
__device__ __half  g_attn[NH * LRES * LRES]; // fp16
__device__ __half  g_wpackT[NWIDE * DM];     // packed fp16 [n][k] (K-major!)
__device__ __half  g_w2T[2 * DM * DM];       // fp16 K-major: qSW^T, O^T

// ---- helpers ----
__device__ __forceinline__ uint32_t f2h2(float a, float b) {
    __half2 h = __floats2half2_rn(a, b);
    return *(uint32_t*)&h;
}
__device__ __forceinline__ void mma_f16(float* c,
    uint32_t a0, uint32_t a1, uint32_t a2, uint32_t a3,
    uint32_t b0, uint32_t b1)
{
    asm volatile(
        "mma.sync.aligned.m16n8k16.row.col.f32.f16.f16.f32 "
        "{%0,%1,%2,%3},{%4,%5,%6,%7},{%8,%9},{%0,%1,%2,%3};"
        : "+f"(c[0]), "+f"(c[1]), "+f"(c[2]), "+f"(c[3])
        : "r"(a0), "r"(a1), "r"(a2), "r"(a3), "r"(b0), "r"(b1));
}
__device__ __forceinline__ void cp16(void* s, const void* g) {
    uint32_t sa = (uint32_t)__cvta_generic_to_shared(s);
    asm volatile("cp.async.cg.shared.global [%0], [%1], 16;" :: "r"(sa), "l"(g));
}
#define CP_COMMIT() asm volatile("cp.async.commit_group;")
#define CP_WAIT(n)  asm volatile("cp.async.wait_group %0;" :: "n"(n))
#define LDU32(p) (*(const uint32_t*)(p))

// =========================================================================
// K0a: packed fp16 weight, K-MAJOR: wpackT[c][k], c = [kSW|Q|K|V|G] cols.
// =========================================================================
__global__ void __launch_bounds__(256) cvt_pack_kernel(
    const float* w0, const float* w1, const float* w2, const float* w3,
    const float* w4, __half* dst)
{
    const int idx = blockIdx.x * 256 + threadIdx.x;   // < 1280*256
    const int c = idx >> 8, k = idx & 255;
    const int seg = c >> 8, cc = c & 255;
    const float* src;
    switch (seg) {
        case 0: src = w0; break; case 1: src = w1; break;
        case 2: src = w2; break; case 3: src = w3; break;
        default: src = w4; break;
    }
    dst[idx] = __float2half(src[k * DM + cc]);
}
// K0b: qSW^T + O^T fp16 K-major. grid (256, 2)
__global__ void __launch_bounds__(256) cvt2_kernel(
    const float* w0, const float* w1, __half* dst)
{
    const int m = blockIdx.y;
    const int idx = blockIdx.x * 256 + threadIdx.x;   // < 65536
    const int n = idx >> 8, k = idx & 255;
    const float* src = (m == 0) ? w0 : w1;
    dst[m * (DM * DM) + idx] = __float2half(src[k * DM + n]);
}

// =========================================================================
// K1: LayerNorm, warp-per-row (D=256), 8 rows/block, writes fp16.
// =========================================================================
__global__ void __launch_bounds__(256) ln_msa_kernel(
    const float* __restrict__ x, const float* __restrict__ g,
    const float* __restrict__ b, __half* __restrict__ out)
{
    const int w = threadIdx.x >> 5, lane = threadIdx.x & 31;
    const size_t row = (size_t)blockIdx.x * 8 + w;
    const float* xr = x + row * DM;
    float4 v0 = *(const float4*)(xr + lane * 4);
    float4 v1 = *(const float4*)(xr + 128 + lane * 4);
    float s  = v0.x + v0.y + v0.z + v0.w + v1.x + v1.y + v1.z + v1.w;
    float s2 = v0.x*v0.x + v0.y*v0.y + v0.z*v0.z + v0.w*v0.w
             + v1.x*v1.x + v1.y*v1.y + v1.z*v1.z + v1.w*v1.w;
    #pragma unroll
    for (int o = 16; o; o >>= 1) {
        s  += __shfl_xor_sync(0xffffffffu, s,  o);
        s2 += __shfl_xor_sync(0xffffffffu, s2, o);
    }
    const float mu   = s * (1.f / DM);
    const float rstd = rsqrtf(s2 * (1.f / DM) - mu * mu + EPS);
    float4 g0 = *(const float4*)(g + lane * 4);
    float4 g1 = *(const float4*)(g + 128 + lane * 4);
    float4 b0 = *(const float4*)(b + lane * 4);
    float4 b1 = *(const float4*)(b + 128 + lane * 4);
    uint2 o0, o1;
    o0.x = f2h2((v0.x - mu)*rstd*g0.x + b0.x, (v0.y - mu)*rstd*g0.y + b0.y);
    o0.y = f2h2((v0.z - mu)*rstd*g0.z + b0.z, (v0.w - mu)*rstd*g0.w + b0.w);
    o1.x = f2h2((v1.x - mu)*rstd*g1.x + b1.x, (v1.y - mu)*rstd*g1.y + b1.y);
    o1.y = f2h2((v1.z - mu)*rstd*g1.z + b1.z, (v1.w - mu)*rstd*g1.w + b1.w);
    *(uint2*)(out + row * DM + lane * 4)       = o0;
    *(uint2*)(out + row * DM + 128 + lane * 4) = o1;
}

// =========================================================================
// W1: fp16 GEMM. Block 128x128, BK=32, 3-stage cp.async, 1 sync/iter.
// A [M][K] row-major fp16, B [N][K] K-MAJOR fp16. 8 warps = 4m x 2n of 32x64.
// MODE 0: fused 5-segment projection epilogue. MODE 1: plain fp32 out.
// =========================================================================
#define WG_LOAD(stg, k0) do {                                                 \
    _Pragma("unroll")                                                         \
    for (int s_ = 0; s_ < 2; s_++) {                                          \
        const int r_ = (tid >> 2) + 64 * s_;                                  \
        const int c_ = (tid & 3) * 8;                                         \
        cp16(&As[stg][r_][c_], A + (size_t)(m0 + r_) * K + (k0) + c_);        \
        cp16(&Bs[stg][r_][c_], B + (size_t)(n0 + r_) * K + (k0) + c_);        \
    }                                                                         \
    CP_COMMIT();                                                              \
} while (0)

template<int MODE>
__global__ void __launch_bounds__(256, 2) wgemm_kernel(
    const __half* __restrict__ A, const __half* __restrict__ B,
    int M, int K, int Nld,
    float* __restrict__ ksw, float* __restrict__ qf,
    __half* __restrict__ ktf, __half* __restrict__ vtf,
    float* __restrict__ gatef,
    const float* __restrict__ bias0, const float* __restrict__ bias1,
    float scaleArg, float* __restrict__ C)
{
    extern __shared__ __half dynh[];
    __half (*As)[128][40] = (__half (*)[128][40])dynh;
    __half (*Bs)[128][40] = (__half (*)[128][40])(dynh + 3 * 128 * 40);
    const int tid = threadIdx.x;
    const int n0 = blockIdx.x * 128;
    const int m0 = blockIdx.y * 128;
    const int lane = tid & 31, w = tid >> 5;
    const int wm = w >> 1, wn = w & 1;
    const int gid = lane >> 2, tig = lane & 3;
    float acc[2][8][4] = {};

    const int T = K >> 5;   // BK=32
    WG_LOAD(0, 0);
    WG_LOAD(1, 32);
    int st = 0, ld = 2;
    for (int t = 0; t < T; t++) {
        if (t + 1 < T) { CP_WAIT(1); } else { CP_WAIT(0); }
        __syncthreads();
        if (t + 2 < T) {
            WG_LOAD(ld, (t + 2) << 5);
            ld = (ld == 2) ? 0 : ld + 1;
        }
        #pragma unroll
        for (int ks = 0; ks < 2; ks++) {
            const int kb = ks * 16;
            uint32_t a[2][4], bfr[8][2];
            #pragma unroll
            for (int mt = 0; mt < 2; mt++) {
                const int rm = wm * 32 + mt * 16 + gid;
                a[mt][0] = LDU32(&As[st][rm    ][kb + 2*tig]);
                a[mt][1] = LDU32(&As[st][rm + 8][kb + 2*tig]);
                a[mt][2] = LDU32(&As[st][rm    ][kb + 2*tig + 8]);
                a[mt][3] = LDU32(&As[st][rm + 8][kb + 2*tig + 8]);
            }
            #pragma unroll
            for (int nt = 0; nt < 8; nt++) {
                const int nc = wn * 64 + nt * 8 + gid;
                bfr[nt][0] = LDU32(&Bs[st][nc][kb + 2*tig]);
                bfr[nt][1] = LDU32(&Bs[st][nc][kb + 2*tig + 8]);
            }
            #pragma unroll
            for (int mt = 0; mt < 2; mt++)
                #pragma unroll
                for (int nt = 0; nt < 8; nt++)
                    mma_f16(acc[mt][nt], a[mt][0], a[mt][1], a[mt][2], a[mt][3],
                            bfr[nt][0], bfr[nt][1]);
        }
        st = (st == 2) ? 0 : st + 1;
    }
    // epilogue
    const int seg = (MODE == 0) ? (blockIdx.x >> 1) : 0;
    #pragma unroll
    for (int mt = 0; mt < 2; mt++) {
        const int r0 = m0 + wm * 32 + mt * 16 + gid;
        #pragma unroll
        for (int nt = 0; nt < 8; nt++) {
            const int col = n0 + wn * 64 + nt * 8 + 2 * tig;
            float v00 = acc[mt][nt][0], v01 = acc[mt][nt][1];
            float v10 = acc[mt][nt][2], v11 = acc[mt][nt][3];
            if (MODE == 0) {
                const int cc = col & 255;
                const size_t p0 = (size_t)r0 * HD + cc;
                const size_t p1 = (size_t)(r0 + 8) * HD + cc;
                switch (seg) {
                    case 0: {
                        const float b0 = bias0[cc], b1 = bias0[cc + 1];
                        *(float2*)(ksw + p0) = make_float2(v00 + b0, v01 + b1);
                        *(float2*)(ksw + p1) = make_float2(v10 + b0, v11 + b1);
                        break;
                    }
                    case 1: {
                        *(float2*)(qf + p0) = make_float2(v00, v01);
                        *(float2*)(qf + p1) = make_float2(v10, v11);
                        break;
                    }
                    case 2: {
                        *(uint32_t*)(ktf + p0) = f2h2(v00 * scaleArg, v01 * scaleArg);
                        *(uint32_t*)(ktf + p1) = f2h2(v10 * scaleArg, v11 * scaleArg);
                        break;
                    }
                    case 3: {
                        *(uint32_t*)(vtf + p0) = f2h2(v00, v01);
                        *(uint32_t*)(vtf + p1) = f2h2(v10, v11);
                        break;
                    }
                    default: {
                        const float b0 = bias1[cc], b1 = bias1[cc + 1];
                        *(float2*)(gatef + p0) = make_float2(1.f/(1.f+expf(-(v00+b0))),
                                                             1.f/(1.f+expf(-(v01+b1))));
                        *(float2*)(gatef + p1) = make_float2(1.f/(1.f+expf(-(v10+b0))),
                                                             1.f/(1.f+expf(-(v11+b1))));
                        break;
                    }
                }
            } else {
                const float b0 = bias0 ? bias0[col] : 0.f;
                const float b1 = bias0 ? bias0[col + 1] : 0.f;
                *(float2*)(C + (size_t)r0 * Nld + col) =
                    make_float2((v00 + b0) * scaleArg, (v01 + b1) * scaleArg);
                *(float2*)(C + (size_t)(r0 + 8) * Nld + col) =
                    make_float2((v10 + b0) * scaleArg, (v11 + b1) * scaleArg);
            }
        }
    }
}
#undef WG_LOAD

// =========================================================================
// K3: seq-weight softmax over n. grid (L, H).
// =========================================================================
__global__ void __launch_bounds__(256) seqw_kernel(
    const float* __restrict__ qsw, const float* __restrict__ ksw,
    float* __restrict__ sw)
{
    const int i = blockIdx.x, h = blockIdx.y;
    const int t = threadIdx.x;            // = n
    __shared__ __align__(16) float qs[DHD];
    __shared__ float red[8];
    if (t < DHD) qs[t] = qsw[(size_t)i * HD + h * DHD + t];
    __syncthreads();
    const float* kp = ksw + ((size_t)t * LRES + i) * HD + h * DHD;
    float dot = 0.f;
    #pragma unroll
    for (int c = 0; c < 8; c++) {
        float4 k4 = *(const float4*)(kp + 4 * c);
        float4 q4 = *(const float4*)(qs + 4 * c);
        dot += k4.x * q4.x + k4.y * q4.y + k4.z * q4.z + k4.w * q4.w;
    }
    const int w = t >> 5, lane = t & 31;
    float mx = dot;
    #pragma unroll
    for (int o = 16; o; o >>= 1) mx = fmaxf(mx, __shfl_xor_sync(0xffffffffu, mx, o));
    if (!lane) red[w] = mx;
    __syncthreads();
    mx = red[0];
    #pragma unroll
    for (int x = 1; x < 8; x++) mx = fmaxf(mx, red[x]);
    const float e = expf(dot - mx);
    float s = e;
    #pragma unroll
    for (int o = 16; o; o >>= 1) s += __shfl_xor_sync(0xffffffffu, s, o);
    __syncthreads();
    if (!lane) red[w] = s;
    __syncthreads();
    float S = 0.f;
    #pragma unroll
    for (int x = 0; x < 8; x++) S += red[x];
    sw[((size_t)t * LRES + i) * NH + h] = e / S;
}

// =========================================================================
// K3b: qw = fp16(q * seq_weight) elementwise.
// =========================================================================
__global__ void __launch_bounds__(256) qw_kernel(
    const float* __restrict__ q, const float* __restrict__ sw,
    __half* __restrict__ qw)
{
    const size_t i4 = (size_t)blockIdx.x * 256 + threadIdx.x;
    const size_t row = i4 >> 6;
    const int h = (int)((i4 >> 3) & 7);
    const float s = sw[row * NH + h];
    float4 v = *(const float4*)(q + i4 * 4);
    uint2 o;
    o.x = f2h2(v.x * s, v.y * s);
    o.y = f2h2(v.z * s, v.w * s);
    *(uint2*)(qw + i4 * 4) = o;
}

// =========================================================================
// K4b: transpose v -> vT[h][n][d][j] fp16. grid (NSEQ, NH), 256 thr.
// =========================================================================
__global__ void __launch_bounds__(256) vtrans_kernel(
    const __half* __restrict__ v, __half* __restrict__ vt)
{
    __shared__ __half tile[DHD][LRES + 8];
    const int n = blockIdx.x, h = blockIdx.y;
    const int tid = threadIdx.x;
    #pragma unroll
    for (int it = 0; it < 6; it++) {
        const int idx = tid + 256 * it;      // 0..1535
        const int j = idx >> 2;
        const int c = (idx & 3) * 8;         // d-chunk
        uint4 val = *(const uint4*)(v + ((size_t)n * LRES + j) * HD + h * DHD + c);
        const __half* hv = (const __half*)&val;
        #pragma unroll
        for (int x = 0; x < 8; x++) tile[c + x][j] = hv[x];
    }
    __syncthreads();
    #pragma unroll
    for (int it = 0; it < 6; it++) {
        const int idx = tid + 256 * it;      // 0..1535
        const int d = idx / 48;
        const int c = (idx % 48) * 8;        // j-chunk
        uint4 val = *(const uint4*)&tile[d][c];
        *(uint4*)(vt + ((size_t)((h * NSEQ + n) * DHD + d)) * LRES + c) = val;
    }
}

// =========================================================================
// T2: logits (fp16 mma). Block 64x64, BK=64 halves (2 n/step), 3-stage.
// grid (6,6,8).
// =========================================================================
#define LG_LOAD(stg, np) do {                                                      \
    const int nb_ = (np) * 2;                                                      \
    _Pragma("unroll")                                                              \
    for (int s_ = 0; s_ < 2; s_++) {                                               \
        const int r_ = (tid >> 3) + 32 * s_;                                       \
        const int col_ = (tid & 7) * 8;                                            \
        const int n_ = nb_ + (col_ >> 5);                                          \
        const int d_ = col_ & 31;                                                  \
        cp16(&As[stg][r_][col_], qw + ((size_t)n_ * LRES + i0 + r_) * HD + h * DHD + d_); \
        cp16(&Bs[stg][r_][col_], kk + ((size_t)n_ * LRES + j0 + r_) * HD + h * DHD + d_); \
    }                                                                              \
    CP_COMMIT();                                                                   \
} while (0)

__global__ void __launch_bounds__(256, 2) logits_tc_kernel(
    const __half* __restrict__ qw, const __half* __restrict__ kk,
    float* __restrict__ out)
{
    extern __shared__ __half dynh[];
    __half (*As)[64][72] = (__half (*)[64][72])dynh;
    __half (*Bs)[64][72] = (__half (*)[64][72])(dynh + 3 * 64 * 72);
    const int tid = threadIdx.x;
    const int i0 = blockIdx.x * 64;
    const int j0 = blockIdx.y * 64;
    const int h  = blockIdx.z;
    const int lane = tid & 31, w = tid >> 5;
    const int wm = w >> 1, wn = w & 1;
    const int gid = lane >> 2, tig = lane & 3;
    float acc[4][4] = {};

    const int T = NSEQ / 2;   // 128
    LG_LOAD(0, 0);
    LG_LOAD(1, 1);
    int st = 0, ld = 2;
    for (int t = 0; t < T; t++) {
        if (t + 1 < T) { CP_WAIT(1); } else { CP_WAIT(0); }
        __syncthreads();
        if (t + 2 < T) {
            LG_LOAD(ld, t + 2);
            ld = (ld == 2) ? 0 : ld + 1;
        }
        #pragma unroll
        for (int ks = 0; ks < 4; ks++) {
            const int kb = ks * 16;
            const int rm = wm * 16 + gid;
            const uint32_t a0 = LDU32(&As[st][rm    ][kb + 2*tig]);
            const uint32_t a1 = LDU32(&As[st][rm + 8][kb + 2*tig]);
            const uint32_t a2 = LDU32(&As[st][rm    ][kb + 2*tig + 8]);
            const uint32_t a3 = LDU32(&As[st][rm + 8][kb + 2*tig + 8]);
            #pragma unroll
            for (int nt = 0; nt < 4; nt++) {
                const int nc = wn * 32 + nt * 8 + gid;
                mma_f16(acc[nt], a0, a1, a2, a3,
                        LDU32(&Bs[st][nc][kb + 2*tig]),
                        LDU32(&Bs[st][nc][kb + 2*tig + 8]));
            }
        }
        st = (st == 2) ? 0 : st + 1;
    }
    const size_t ob = (size_t)h * LRES * LRES;
    const int r0 = i0 + wm * 16 + gid;
    #pragma unroll
    for (int nt = 0; nt < 4; nt++) {
        const int col = j0 + wn * 32 + nt * 8 + 2 * tig;
        *(float2*)(out + ob + (size_t)r0 * LRES + col)     = make_float2(acc[nt][0], acc[nt][1]);
        *(float2*)(out + ob + (size_t)(r0+8) * LRES + col) = make_float2(acc[nt][2], acc[nt][3]);
    }
}
#undef LG_LOAD

// =========================================================================
// K6: fused pair-bias + softmax -> fp16 attn. One block per i (256 thr).
// =========================================================================
__global__ void __launch_bounds__(256) pairsoftmax_kernel(
    const float* __restrict__ pair, const float* __restrict__ g,
    const float* __restrict__ b, const float* __restrict__ Wb,
    const float* __restrict__ logits, __half* __restrict__ attn)
{
    __shared__ float bias_s[LRES][NH + 1];
    const int i = blockIdx.x;
    const int w = threadIdx.x >> 5, lane = threadIdx.x & 31;

    for (int j = w; j < LRES; j += 8) {
        const size_t p = (size_t)i * LRES + j;
        float4 v = *(const float4*)(pair + p * DP + lane * 4);
        float s  = v.x + v.y + v.z + v.w;
        float s2 = v.x*v.x + v.y*v.y + v.z*v.z + v.w*v.w;
        #pragma unroll
        for (int o = 16; o; o >>= 1) {
            s  += __shfl_xor_sync(0xffffffffu, s,  o);
            s2 += __shfl_xor_sync(0xffffffffu, s2, o);
        }
        const float mu   = s * (1.f / DP);
        const float rstd = rsqrtf(s2 * (1.f / DP) - mu * mu + EPS);
        float xv[4] = {v.x, v.y, v.z, v.w};
        float acc[8] = {};
        #pragma unroll
        for (int c = 0; c < 4; c++) {
            const int d = lane * 4 + c;
            const float y = (xv[c] - mu) * rstd * g[d] + b[d];
            const float* wr = Wb + d * NH;
            #pragma unroll
            for (int hh = 0; hh < 8; hh++) acc[hh] = fmaf(y, wr[hh], acc[hh]);
        }
        #pragma unroll
        for (int hh = 0; hh < 8; hh++) {
            float a = acc[hh];
            #pragma unroll
            for (int o = 16; o; o >>= 1) a += __shfl_xor_sync(0xffffffffu, a, o);
            if (lane == hh) bias_s[j][hh] = a;
        }
    }
    __syncthreads();

    // phase 2: warp w = head h; each lane handles 6 j-pairs
    const int h = w;
    const size_t base = ((size_t)h * LRES + i) * LRES;
    float x[12];
    #pragma unroll
    for (int r = 0; r < 6; r++) {
        const int j = 2 * lane + 64 * r;
        float2 lg = *(const float2*)(logits + base + j);
        x[2*r]   = lg.x + bias_s[j][h];
        x[2*r+1] = lg.y + bias_s[j + 1][h];
    }
    float mx = x[0];
    #pragma unroll
    for (int r = 1; r < 12; r++) mx = fmaxf(mx, x[r]);
    #pragma unroll
    for (int o = 16; o; o >>= 1) mx = fmaxf(mx, __shfl_xor_sync(0xffffffffu, mx, o));
    float e[12], sum = 0.f;
    #pragma unroll
    for (int r = 0; r < 12; r++) { e[r] = expf(x[r] - mx); sum += e[r]; }
    #pragma unroll
    for (int o = 16; o; o >>= 1) sum += __shfl_xor_sync(0xffffffffu, sum, o);
    const float inv = 1.f / sum;
    #pragma unroll
    for (int r = 0; r < 6; r++) {
        *(uint32_t*)(attn + base + 2 * lane + 64 * r) =
            f2h2(e[2*r] * inv, e[2*r+1] * inv);
    }
}

// =========================================================================
// T3: aog = fp16(gate * (attn @ vT^T)). Block 128(i) x 64(nd), BK=32(j).
// grid (3, 128, 8). B = vT[h][n][d][j] K-major.
// =========================================================================
#define AO_LOAD(stg, j0) do {                                                       \
    _Pragma("unroll")                                                               \
    for (int s_ = 0; s_ < 2; s_++) {                                                \
        const int r_ = (tid >> 2) + 64 * s_;                                        \
        const int c_ = (tid & 3) * 8;                                               \
        cp16(&As[stg][r_][c_], Ah + (size_t)(i0 + r_) * LRES + (j0) + c_);          \
    }                                                                               \
    {                                                                               \
        const int rB_ = tid >> 2;        /* 0..63 = nd */                           \
        const int cB_ = (tid & 3) * 8;                                              \
        const int nB_ = (blockIdx.y << 1) + (rB_ >> 5);                             \
        const int dB_ = rB_ & 31;                                                   \
        cp16(&Bs[stg][rB_][cB_],                                                    \
             vt + ((size_t)((h * NSEQ + nB_) * DHD + dB_)) * LRES + (j0) + cB_);    \
    }                                                                               \
    CP_COMMIT();                                                                    \
} while (0)

__global__ void __launch_bounds__(256, 2) attnout_tc_kernel(
    const __half* __restrict__ attn, const __half* __restrict__ vt,
    const float* __restrict__ gate, __half* __restrict__ aog)
{
    __shared__ __half As[3][128][40];
    __shared__ __half Bs[3][64][40];
    const int tid = threadIdx.x;
    const int i0 = blockIdx.x * 128;
    const int h  = blockIdx.z;
    const int lane = tid & 31, w = tid >> 5;
    const int wm = w >> 1, wn = w & 1;
    const int gid = lane >> 2, tig = lane & 3;
    const __half* Ah = attn + (size_t)h * LRES * LRES;
    float acc[2][4][4] = {};

    const int T = LRES / 32;  // 12
    AO_LOAD(0, 0);
    AO_LOAD(1, 32);
    int st = 0, ld = 2;
    for (int t = 0; t < T; t++) {
        if (t + 1 < T) { CP_WAIT(1); } else { CP_WAIT(0); }
        __syncthreads();
        if (t + 2 < T) {
            AO_LOAD(ld, (t + 2) * 32);
            ld = (ld == 2) ? 0 : ld + 1;
        }
        #pragma unroll
        for (int ks = 0; ks < 2; ks++) {
            const int kb = ks * 16;
            uint32_t a[2][4], bfr[4][2];
            #pragma unroll
            for (int mt = 0; mt < 2; mt++) {
                const int rm = wm * 32 + mt * 16 + gid;
                a[mt][0] = LDU32(&As[st][rm    ][kb + 2*tig]);
                a[mt][1] = LDU32(&As[st][rm + 8][kb + 2*tig]);
                a[mt][2] = LDU32(&As[st][rm    ][kb + 2*tig + 8]);
                a[mt][3] = LDU32(&As[st][rm + 8][kb + 2*tig + 8]);
            }
            #pragma unroll
            for (int nt = 0; nt < 4; nt++) {
                const int nc = wn * 32 + nt * 8 + gid;
                bfr[nt][0] = LDU32(&Bs[st][nc][kb + 2*tig]);
                bfr[nt][1] = LDU32(&Bs[st][nc][kb + 2*tig + 8]);
            }
            #pragma unroll
            for (int mt = 0; mt < 2; mt++)
                #pragma unroll
                for (int nt = 0; nt < 4; nt++)
                    mma_f16(acc[mt][nt], a[mt][0], a[mt][1], a[mt][2], a[mt][3],
                            bfr[nt][0], bfr[nt][1]);
        }
        st = (st == 2) ? 0 : st + 1;
    }
    #pragma unroll
    for (int mt = 0; mt < 2; mt++) {
        const int r0 = i0 + wm * 32 + mt * 16 + gid;
        #pragma unroll
        for (int nt = 0; nt < 4; nt++) {
            const int col = wn * 32 + nt * 8 + 2 * tig;      // nd within 64
            const int nOut = (blockIdx.y << 1) + (col >> 5);
            const int d = col & 31;
            const size_t p0 = ((size_t)nOut * LRES + r0) * HD + h * DHD + d;
            const size_t p1 = ((size_t)nOut * LRES + r0 + 8) * HD + h * DHD + d;
            const float2 gA = *(const float2*)(gate + p0);
            const float2 gB = *(const float2*)(gate + p1);
            *(uint32_t*)(aog + p0) = f2h2(acc[mt][nt][0] * gA.x, acc[mt][nt][1] * gA.y);
            *(uint32_t*)(aog + p1) = f2h2(acc[mt][nt][2] * gB.x, acc[mt][nt][3] * gB.y);
        }
    }
}
#undef AO_LOAD

// =========================================================================
// launcher
// =========================================================================
extern "C" void kernel_launch(void* const* d_in, const int* in_sizes, int n_in,
                              void* d_out, int out_size)
{
    const float* msa       = (const float*)d_in[0];
    const float* pair      = (const float*)d_in[1];
    const float* ln_msa_g  = (const float*)d_in[2];
    const float* ln_msa_b  = (const float*)d_in[3];
    const float* ln_pair_g = (const float*)d_in[4];
    const float* ln_pair_b = (const float*)d_in[5];
    const float* Wq_sw     = (const float*)d_in[6];
    const float* bq_sw     = (const float*)d_in[7];
    const float* Wk_sw     = (const float*)d_in[8];
    const float* bk_sw     = (const float*)d_in[9];
    const float* Wq        = (const float*)d_in[10];
    const float* Wk        = (const float*)d_in[11];
    const float* Wv        = (const float*)d_in[12];
    const float* Wb        = (const float*)d_in[13];
    const float* Wg        = (const float*)d_in[14];
    const float* bg        = (const float*)d_in[15];
    const float* Wo        = (const float*)d_in[16];
    const float* bo        = (const float*)d_in[17];
    float* out = (float*)d_out;

    __half *m_, *qw_, *k_, *v_, *vt_, *aog_, *attn_, *wpackT_, *w2T_;
    float *qsw_, *ksw_, *q_, *gate_, *sw_, *logits_;
    cudaGetSymbolAddress((void**)&m_,      g_m);
    cudaGetSymbolAddress((void**)&qsw_,    g_qsw);
    cudaGetSymbolAddress((void**)&ksw_,    g_ksw);
    cudaGetSymbolAddress((void**)&q_,      g_q);
    cudaGetSymbolAddress((void**)&qw_,     g_qw);
    cudaGetSymbolAddress((void**)&k_,      g_k);
    cudaGetSymbolAddress((void**)&v_,      g_v);
    cudaGetSymbolAddress((void**)&vt_,     g_vt);
    cudaGetSymbolAddress((void**)&gate_,   g_gate);
    cudaGetSymbolAddress((void**)&aog_,    g_aog);
    cudaGetSymbolAddress((void**)&sw_,     g_sw);
    cudaGetSymbolAddress((void**)&logits_, g_logits);
    cudaGetSymbolAddress((void**)&attn_,   g_attn);
    cudaGetSymbolAddress((void**)&wpackT_, g_wpackT);
    cudaGetSymbolAddress((void**)&w2T_,    g_w2T);

    const float scale = 0.17677669529663687f;  // 1/sqrt(32)
    const __half *WqSWT = w2T_, *WOT = w2T_ + DM * DM;

    const int WG_SMEM = (3 * 128 * 40 * 2) * 2;   // 61440
    const int LG_SMEM = (3 * 64 * 72 * 2) * 2;    // 55296
    cudaFuncSetAttribute((const void*)wgemm_kernel<0>,
        cudaFuncAttributeMaxDynamicSharedMemorySize, WG_SMEM);
    cudaFuncSetAttribute((const void*)wgemm_kernel<1>,
        cudaFuncAttributeMaxDynamicSharedMemorySize, WG_SMEM);
    cudaFuncSetAttribute((const void*)logits_tc_kernel,
        cudaFuncAttributeMaxDynamicSharedMemorySize, LG_SMEM);

    // preprocessing: pack transposed fp16 weights, LN
    cvt_pack_kernel<<<(DM * NWIDE) / 256, 256>>>(Wk_sw, Wq, Wk, Wv, Wg, wpackT_);
    cvt2_kernel<<<dim3(DM * DM / 256, 2), 256>>>(Wq_sw, Wo, w2T_);
    ln_msa_kernel<<<NLROWS / 8, 256>>>(msa, ln_msa_g, ln_msa_b, m_);

    // fused 5-way projection
    wgemm_kernel<0><<<dim3(NWIDE / 128, NLROWS / 128), 256, WG_SMEM>>>(
        m_, wpackT_, NLROWS, DM, NWIDE,
        ksw_, q_, k_, v_, gate_, bk_sw, bg, scale, nullptr);

    // qsw: (m0 @ Wq_sw + bq_sw) * scale
    wgemm_kernel<1><<<dim3(HD / 128, LRES / 128), 256, WG_SMEM>>>(
        m_, WqSWT, LRES, DM, HD,
        nullptr, nullptr, nullptr, nullptr, nullptr, bq_sw, nullptr, scale, qsw_);

    // seq weights + weighted q + v transpose
    seqw_kernel<<<dim3(LRES, NH), 256>>>(qsw_, ksw_, sw_);
    qw_kernel<<<(NLROWS * HD / 4) / 256, 256>>>(q_, sw_, qw_);
    vtrans_kernel<<<dim3(NSEQ, NH), 256>>>(v_, vt_);

    // logits
    logits_tc_kernel<<<dim3(LRES / 64, LRES / 64, NH), 256, LG_SMEM>>>(qw_, k_, logits_);

    // fused pair bias + softmax (fp16 attn)
    pairsoftmax_kernel<<<LRES, 256>>>(pair, ln_pair_g, ln_pair_b, Wb, logits_, attn_);

    // attn @ v (gate fused)
    attnout_tc_kernel<<<dim3(LRES / 128, NSEQ / 2, NH), 256>>>(attn_, vt_, gate_, aog_);

    // final: aog @ Wo + bo
    wgemm_kernel<1><<<dim3(DM / 128, NLROWS / 128), 256, WG_SMEM>>>(
        aog_, WOT, NLROWS, DM, DM,
        nullptr, nullptr, nullptr, nullptr, nullptr, bo, nullptr, 1.f, out);
}

// round 8
// speedup vs baseline: 2.2517x; 1.0757x over previous
#include <cuda_runtime.h>
#include <cuda_fp16.h>
#include <math.h>
#include <stdint.h>

// Problem constants
#define NSEQ 256
#define LRES 384
#define DM   256
#define DP   128
#define NH   8
#define DHD  32
#define HD   256           // NH*DHD
#define NLROWS (NSEQ*LRES) // 98304
#define EPS 1e-5f
#define NWIDE 1280         // 5 fused projection outputs

// -------- scratch (device globals) --------
__device__ __half  g_m[NLROWS * DM];        // LN(msa), fp16
__device__ float   g_qsw[LRES * HD];        // q_sw (scaled), fp32
__device__ float   g_ksw[NLROWS * HD];      // k_sw, fp32
__device__ float   g_q[NLROWS * HD];        // m@Wq, fp32
__device__ __half  g_qw[NLROWS * HD];       // (q * seq_weight), fp16
__device__ __half  g_k[NLROWS * HD];        // m@Wk * scale, fp16
__device__ __half  g_v[NLROWS * HD];        // m@Wv, fp16 [n,j,h,d]
__device__ __half  g_vt[NH * NSEQ * DHD * LRES]; // v^T: [h][n][d][j], fp16
__device__ float   g_gate[NLROWS * HD];     // sigmoid(m@Wg+bg), fp32
__device__ __half  g_aog[NLROWS * HD];      // (attn@v)*gate, fp16
__device__ float   g_sw[NLROWS * NH];       // seq weights
__device__ float   g_logits[NH * LRES * LRES];
__device__ __half  g_attn[NH * LRES * LRES]; // fp16
__device__ __half  g_wpackT[NWIDE * DM];     // packed fp16 [n][k] (K-major!)
__device__ __half  g_w2T[2 * DM * DM];       // fp16 K-major: qSW^T, O^T

// ---- helpers ----
__device__ __forceinline__ uint32_t f2h2(float a, float b) {
    __half2 h = __floats2half2_rn(a, b);
    return *(uint32_t*)&h;
}
__device__ __forceinline__ void mma_f16(float* c,
    uint32_t a0, uint32_t a1, uint32_t a2, uint32_t a3,
    uint32_t b0, uint32_t b1)
{
    asm volatile(
        "mma.sync.aligned.m16n8k16.row.col.f32.f16.f16.f32 "
        "{%0,%1,%2,%3},{%4,%5,%6,%7},{%8,%9},{%0,%1,%2,%3};"
        : "+f"(c[0]), "+f"(c[1]), "+f"(c[2]), "+f"(c[3])
        : "r"(a0), "r"(a1), "r"(a2), "r"(a3), "r"(b0), "r"(b1));
}
__device__ __forceinline__ void cp16(void* s, const void* g) {
    uint32_t sa = (uint32_t)__cvta_generic_to_shared(s);
    asm volatile("cp.async.cg.shared.global [%0], [%1], 16;" :: "r"(sa), "l"(g));
}
__device__ __forceinline__ void ldsm_x4(uint32_t& r0, uint32_t& r1,
                                        uint32_t& r2, uint32_t& r3, const void* p)
{
    uint32_t a = (uint32_t)__cvta_generic_to_shared(p);
    asm volatile("ldmatrix.sync.aligned.m8n8.x4.shared.b16 {%0,%1,%2,%3}, [%4];"
        : "=r"(r0), "=r"(r1), "=r"(r2), "=r"(r3) : "r"(a));
}
#define CP_COMMIT() asm volatile("cp.async.commit_group;")
#define CP_WAIT(n)  asm volatile("cp.async.wait_group %0;" :: "n"(n))

// =========================================================================
// K0a: packed fp16 weight, K-MAJOR: wpackT[c][k], c = [kSW|Q|K|V|G] cols.
// =========================================================================
__global__ void __launch_bounds__(256) cvt_pack_kernel(
    const float* w0, const float* w1, const float* w2, const float* w3,
    const float* w4, __half* dst)
{
    const int idx = blockIdx.x * 256 + threadIdx.x;   // < 1280*256
    const int c = idx >> 8, k = idx & 255;
    const int seg = c >> 8, cc = c & 255;
    const float* src;
    switch (seg) {
        case 0: src = w0; break; case 1: src = w1; break;
        case 2: src = w2; break; case 3: src = w3; break;
        default: src = w4; break;
    }
    dst[idx] = __float2half(src[k * DM + cc]);
}
// K0b: qSW^T + O^T fp16 K-major. grid (256, 2)
__global__ void __launch_bounds__(256) cvt2_kernel(
    const float* w0, const float* w1, __half* dst)
{
    const int m = blockIdx.y;
    const int idx = blockIdx.x * 256 + threadIdx.x;   // < 65536
    const int n = idx >> 8, k = idx & 255;
    const float* src = (m == 0) ? w0 : w1;
    dst[m * (DM * DM) + idx] = __float2half(src[k * DM + n]);
}

// =========================================================================
// K1: LayerNorm, warp-per-row (D=256), 8 rows/block, writes fp16.
// =========================================================================
__global__ void __launch_bounds__(256) ln_msa_kernel(
    const float* __restrict__ x, const float* __restrict__ g,
    const float* __restrict__ b, __half* __restrict__ out)
{
    const int w = threadIdx.x >> 5, lane = threadIdx.x & 31;
    const size_t row = (size_t)blockIdx.x * 8 + w;
    const float* xr = x + row * DM;
    float4 v0 = *(const float4*)(xr + lane * 4);
    float4 v1 = *(const float4*)(xr + 128 + lane * 4);
    float s  = v0.x + v0.y + v0.z + v0.w + v1.x + v1.y + v1.z + v1.w;
    float s2 = v0.x*v0.x + v0.y*v0.y + v0.z*v0.z + v0.w*v0.w
             + v1.x*v1.x + v1.y*v1.y + v1.z*v1.z + v1.w*v1.w;
    #pragma unroll
    for (int o = 16; o; o >>= 1) {
        s  += __shfl_xor_sync(0xffffffffu, s,  o);
        s2 += __shfl_xor_sync(0xffffffffu, s2, o);
    }
    const float mu   = s * (1.f / DM);
    const float rstd = rsqrtf(s2 * (1.f / DM) - mu * mu + EPS);
    float4 g0 = *(const float4*)(g + lane * 4);
    float4 g1 = *(const float4*)(g + 128 + lane * 4);
    float4 b0 = *(const float4*)(b + lane * 4);
    float4 b1 = *(const float4*)(b + 128 + lane * 4);
    uint2 o0, o1;
    o0.x = f2h2((v0.x - mu)*rstd*g0.x + b0.x, (v0.y - mu)*rstd*g0.y + b0.y);
    o0.y = f2h2((v0.z - mu)*rstd*g0.z + b0.z, (v0.w - mu)*rstd*g0.w + b0.w);
    o1.x = f2h2((v1.x - mu)*rstd*g1.x + b1.x, (v1.y - mu)*rstd*g1.y + b1.y);
    o1.y = f2h2((v1.z - mu)*rstd*g1.z + b1.z, (v1.w - mu)*rstd*g1.w + b1.w);
    *(uint2*)(out + row * DM + lane * 4)       = o0;
    *(uint2*)(out + row * DM + 128 + lane * 4) = o1;
}

// =========================================================================
// W1: fp16 GEMM + ldmatrix. Block 128x128, BK=32, 3-stage, 1 sync/iter.
// A [M][K] row-major fp16, B [N][K] K-major fp16. 8 warps = 4m x 2n of 32x64.
// MODE 0: fused 5-segment projection epilogue. MODE 1: plain fp32 out.
// =========================================================================
#define WG_LOAD(stg, k0) do {                                                 \
    _Pragma("unroll")                                                         \
    for (int s_ = 0; s_ < 2; s_++) {                                          \
        const int r_ = (tid >> 2) + 64 * s_;                                  \
        const int c_ = (tid & 3) * 8;                                         \
        cp16(&As[stg][r_][c_], A + (size_t)(m0 + r_) * K + (k0) + c_);        \
        cp16(&Bs[stg][r_][c_], B + (size_t)(n0 + r_) * K + (k0) + c_);        \
    }                                                                         \
    CP_COMMIT();                                                              \
} while (0)

template<int MODE>
__global__ void __launch_bounds__(256, 2) wgemm_kernel(
    const __half* __restrict__ A, const __half* __restrict__ B,
    int M, int K, int Nld,
    float* __restrict__ ksw, float* __restrict__ qf,
    __half* __restrict__ ktf, __half* __restrict__ vtf,
    float* __restrict__ gatef,
    const float* __restrict__ bias0, const float* __restrict__ bias1,
    float scaleArg, float* __restrict__ C)
{
    extern __shared__ __half dynh[];
    __half (*As)[128][40] = (__half (*)[128][40])dynh;
    __half (*Bs)[128][40] = (__half (*)[128][40])(dynh + 3 * 128 * 40);
    const int tid = threadIdx.x;
    const int n0 = blockIdx.x * 128;
    const int m0 = blockIdx.y * 128;
    const int lane = tid & 31, w = tid >> 5;
    const int wm = w >> 1, wn = w & 1;
    const int gid = lane >> 2, tig = lane & 3;
    // ldmatrix lane addressing
    const int lrow = lane & 7, lgrp = lane >> 3;
    const int arow = wm * 32 + lrow + ((lgrp & 1) ? 8 : 0);
    const int acol = (lgrp & 2) ? 8 : 0;
    const int brow = wn * 64 + lrow + ((lgrp >> 1) ? 8 : 0);
    const int bcol = (lgrp & 1) ? 8 : 0;
    float acc[2][8][4] = {};

    const int T = K >> 5;   // BK=32
    WG_LOAD(0, 0);
    WG_LOAD(1, 32);
    int st = 0, ld = 2;
    for (int t = 0; t < T; t++) {
        if (t + 1 < T) { CP_WAIT(1); } else { CP_WAIT(0); }
        __syncthreads();
        if (t + 2 < T) {
            WG_LOAD(ld, (t + 2) << 5);
            ld = (ld == 2) ? 0 : ld + 1;
        }
        #pragma unroll
        for (int ks = 0; ks < 2; ks++) {
            const int kb = ks * 16;
            uint32_t a[2][4], bfr[8][2];
            #pragma unroll
            for (int mt = 0; mt < 2; mt++)
                ldsm_x4(a[mt][0], a[mt][1], a[mt][2], a[mt][3],
                        &As[st][arow + mt * 16][kb + acol]);
            #pragma unroll
            for (int p = 0; p < 4; p++)
                ldsm_x4(bfr[2*p][0], bfr[2*p][1], bfr[2*p+1][0], bfr[2*p+1][1],
                        &Bs[st][brow + p * 16][kb + bcol]);
            #pragma unroll
            for (int mt = 0; mt < 2; mt++)
                #pragma unroll
                for (int nt = 0; nt < 8; nt++)
                    mma_f16(acc[mt][nt], a[mt][0], a[mt][1], a[mt][2], a[mt][3],
                            bfr[nt][0], bfr[nt][1]);
        }
        st = (st == 2) ? 0 : st + 1;
    }
    // epilogue
    const int seg = (MODE == 0) ? (blockIdx.x >> 1) : 0;
    #pragma unroll
    for (int mt = 0; mt < 2; mt++) {
        const int r0 = m0 + wm * 32 + mt * 16 + gid;
        #pragma unroll
        for (int nt = 0; nt < 8; nt++) {
            const int col = n0 + wn * 64 + nt * 8 + 2 * tig;
            float v00 = acc[mt][nt][0], v01 = acc[mt][nt][1];
            float v10 = acc[mt][nt][2], v11 = acc[mt][nt][3];
            if (MODE == 0) {
                const int cc = col & 255;
                const size_t p0 = (size_t)r0 * HD + cc;
                const size_t p1 = (size_t)(r0 + 8) * HD + cc;
                switch (seg) {
                    case 0: {
                        const float b0 = bias0[cc], b1 = bias0[cc + 1];
                        *(float2*)(ksw + p0) = make_float2(v00 + b0, v01 + b1);
                        *(float2*)(ksw + p1) = make_float2(v10 + b0, v11 + b1);
                        break;
                    }
                    case 1: {
                        *(float2*)(qf + p0) = make_float2(v00, v01);
                        *(float2*)(qf + p1) = make_float2(v10, v11);
                        break;
                    }
                    case 2: {
                        *(uint32_t*)(ktf + p0) = f2h2(v00 * scaleArg, v01 * scaleArg);
                        *(uint32_t*)(ktf + p1) = f2h2(v10 * scaleArg, v11 * scaleArg);
                        break;
                    }
                    case 3: {
                        *(uint32_t*)(vtf + p0) = f2h2(v00, v01);
                        *(uint32_t*)(vtf + p1) = f2h2(v10, v11);
                        break;
                    }
                    default: {
                        const float b0 = bias1[cc], b1 = bias1[cc + 1];
                        *(float2*)(gatef + p0) = make_float2(1.f/(1.f+expf(-(v00+b0))),
                                                             1.f/(1.f+expf(-(v01+b1))));
                        *(float2*)(gatef + p1) = make_float2(1.f/(1.f+expf(-(v10+b0))),
                                                             1.f/(1.f+expf(-(v11+b1))));
                        break;
                    }
                }
            } else {
                const float b0 = bias0 ? bias0[col] : 0.f;
                const float b1 = bias0 ? bias0[col + 1] : 0.f;
                *(float2*)(C + (size_t)r0 * Nld + col) =
                    make_float2((v00 + b0) * scaleArg, (v01 + b1) * scaleArg);
                *(float2*)(C + (size_t)(r0 + 8) * Nld + col) =
                    make_float2((v10 + b0) * scaleArg, (v11 + b1) * scaleArg);
            }
        }
    }
}
#undef WG_LOAD

// =========================================================================
// K3: seq-weight softmax over n. grid (L, H).
// =========================================================================
__global__ void __launch_bounds__(256) seqw_kernel(
    const float* __restrict__ qsw, const float* __restrict__ ksw,
    float* __restrict__ sw)
{
    const int i = blockIdx.x, h = blockIdx.y;
    const int t = threadIdx.x;            // = n
    __shared__ __align__(16) float qs[DHD];
    __shared__ float red[8];
    if (t < DHD) qs[t] = qsw[(size_t)i * HD + h * DHD + t];
    __syncthreads();
    const float* kp = ksw + ((size_t)t * LRES + i) * HD + h * DHD;
    float dot = 0.f;
    #pragma unroll
    for (int c = 0; c < 8; c++) {
        float4 k4 = *(const float4*)(kp + 4 * c);
        float4 q4 = *(const float4*)(qs + 4 * c);
        dot += k4.x * q4.x + k4.y * q4.y + k4.z * q4.z + k4.w * q4.w;
    }
    const int w = t >> 5, lane = t & 31;
    float mx = dot;
    #pragma unroll
    for (int o = 16; o; o >>= 1) mx = fmaxf(mx, __shfl_xor_sync(0xffffffffu, mx, o));
    if (!lane) red[w] = mx;
    __syncthreads();
    mx = red[0];
    #pragma unroll
    for (int x = 1; x < 8; x++) mx = fmaxf(mx, red[x]);
    const float e = expf(dot - mx);
    float s = e;
    #pragma unroll
    for (int o = 16; o; o >>= 1) s += __shfl_xor_sync(0xffffffffu, s, o);
    __syncthreads();
    if (!lane) red[w] = s;
    __syncthreads();
    float S = 0.f;
    #pragma unroll
    for (int x = 0; x < 8; x++) S += red[x];
    sw[((size_t)t * LRES + i) * NH + h] = e / S;
}

// =========================================================================
// K3b: qw = fp16(q * seq_weight) elementwise.
// =========================================================================
__global__ void __launch_bounds__(256) qw_kernel(
    const float* __restrict__ q, const float* __restrict__ sw,
    __half* __restrict__ qw)
{
    const size_t i4 = (size_t)blockIdx.x * 256 + threadIdx.x;
    const size_t row = i4 >> 6;
    const int h = (int)((i4 >> 3) & 7);
    const float s = sw[row * NH + h];
    float4 v = *(const float4*)(q + i4 * 4);
    uint2 o;
    o.x = f2h2(v.x * s, v.y * s);
    o.y = f2h2(v.z * s, v.w * s);
    *(uint2*)(qw + i4 * 4) = o;
}

// =========================================================================
// K4b: transpose v -> vT[h][n][d][j] fp16. grid (NSEQ, NH), 256 thr.
// =========================================================================
__global__ void __launch_bounds__(256) vtrans_kernel(
    const __half* __restrict__ v, __half* __restrict__ vt)
{
    __shared__ __half tile[DHD][LRES + 8];
    const int n = blockIdx.x, h = blockIdx.y;
    const int tid = threadIdx.x;
    #pragma unroll
    for (int it = 0; it < 6; it++) {
        const int idx = tid + 256 * it;      // 0..1535
        const int j = idx >> 2;
        const int c = (idx & 3) * 8;         // d-chunk
        uint4 val = *(const uint4*)(v + ((size_t)n * LRES + j) * HD + h * DHD + c);
        const __half* hv = (const __half*)&val;
        #pragma unroll
        for (int x = 0; x < 8; x++) tile[c + x][j] = hv[x];
    }
    __syncthreads();
    #pragma unroll
    for (int it = 0; it < 6; it++) {
        const int idx = tid + 256 * it;      // 0..1535
        const int d = idx / 48;
        const int c = (idx % 48) * 8;        // j-chunk
        uint4 val = *(const uint4*)&tile[d][c];
        *(uint4*)(vt + ((size_t)((h * NSEQ + n) * DHD + d)) * LRES + c) = val;
    }
}

// =========================================================================
// T2: logits (fp16 mma + ldmatrix). Block 64x64, BK=64 halves, 3-stage.
// grid (6,6,8).
// =========================================================================
#define LG_LOAD(stg, np) do {                                                      \
    const int nb_ = (np) * 2;                                                      \
    _Pragma("unroll")                                                              \
    for (int s_ = 0; s_ < 2; s_++) {                                               \
        const int r_ = (tid >> 3) + 32 * s_;                                       \
        const int col_ = (tid & 7) * 8;                                            \
        const int n_ = nb_ + (col_ >> 5);                                          \
        const int d_ = col_ & 31;                                                  \
        cp16(&As[stg][r_][col_], qw + ((size_t)n_ * LRES + i0 + r_) * HD + h * DHD + d_); \
        cp16(&Bs[stg][r_][col_], kk + ((size_t)n_ * LRES + j0 + r_) * HD + h * DHD + d_); \
    }                                                                              \
    CP_COMMIT();                                                                   \
} while (0)

__global__ void __launch_bounds__(256, 2) logits_tc_kernel(
    const __half* __restrict__ qw, const __half* __restrict__ kk,
    float* __restrict__ out)
{
    extern __shared__ __half dynh[];
    __half (*As)[64][72] = (__half (*)[64][72])dynh;
    __half (*Bs)[64][72] = (__half (*)[64][72])(dynh + 3 * 64 * 72);
    const int tid = threadIdx.x;
    const int i0 = blockIdx.x * 64;
    const int j0 = blockIdx.y * 64;
    const int h  = blockIdx.z;
    const int lane = tid & 31, w = tid >> 5;
    const int wm = w >> 1, wn = w & 1;
    const int gid = lane >> 2, tig = lane & 3;
    const int lrow = lane & 7, lgrp = lane >> 3;
    const int arow = wm * 16 + lrow + ((lgrp & 1) ? 8 : 0);
    const int acol = (lgrp & 2) ? 8 : 0;
    const int brow = wn * 32 + lrow + ((lgrp >> 1) ? 8 : 0);
    const int bcol = (lgrp & 1) ? 8 : 0;
    float acc[4][4] = {};

    const int T = NSEQ / 2;   // 128
    LG_LOAD(0, 0);
    LG_LOAD(1, 1);
    int st = 0, ld = 2;
    for (int t = 0; t < T; t++) {
        if (t + 1 < T) { CP_WAIT(1); } else { CP_WAIT(0); }
        __syncthreads();
        if (t + 2 < T) {
            LG_LOAD(ld, t + 2);
            ld = (ld == 2) ? 0 : ld + 1;
        }
        #pragma unroll
        for (int ks = 0; ks < 4; ks++) {
            const int kb = ks * 16;
            uint32_t a[4], bfr[4][2];
            ldsm_x4(a[0], a[1], a[2], a[3], &As[st][arow][kb + acol]);
            #pragma unroll
            for (int p = 0; p < 2; p++)
                ldsm_x4(bfr[2*p][0], bfr[2*p][1], bfr[2*p+1][0], bfr[2*p+1][1],
                        &Bs[st][brow + p * 16][kb + bcol]);
            #pragma unroll
            for (int nt = 0; nt < 4; nt++)
                mma_f16(acc[nt], a[0], a[1], a[2], a[3], bfr[nt][0], bfr[nt][1]);
        }
        st = (st == 2) ? 0 : st + 1;
    }
    const size_t ob = (size_t)h * LRES * LRES;
    const int r0 = i0 + wm * 16 + gid;
    #pragma unroll
    for (int nt = 0; nt < 4; nt++) {
        const int col = j0 + wn * 32 + nt * 8 + 2 * tig;
        *(float2*)(out + ob + (size_t)r0 * LRES + col)     = make_float2(acc[nt][0], acc[nt][1]);
        *(float2*)(out + ob + (size_t)(r0+8) * LRES + col) = make_float2(acc[nt][2], acc[nt][3]);
    }
}
#undef LG_LOAD

// =========================================================================
// K6: fused pair-bias + softmax -> fp16 attn. One block per i (256 thr).
// =========================================================================
__global__ void __launch_bounds__(256) pairsoftmax_kernel(
    const float* __restrict__ pair, const float* __restrict__ g,
    const float* __restrict__ b, const float* __restrict__ Wb,
    const float* __restrict__ logits, __half* __restrict__ attn)
{
    __shared__ float bias_s[LRES][NH + 1];
    const int i = blockIdx.x;
    const int w = threadIdx.x >> 5, lane = threadIdx.x & 31;

    for (int j = w; j < LRES; j += 8) {
        const size_t p = (size_t)i * LRES + j;
        float4 v = *(const float4*)(pair + p * DP + lane * 4);
        float s  = v.x + v.y + v.z + v.w;
        float s2 = v.x*v.x + v.y*v.y + v.z*v.z + v.w*v.w;
        #pragma unroll
        for (int o = 16; o; o >>= 1) {
            s  += __shfl_xor_sync(0xffffffffu, s,  o);
            s2 += __shfl_xor_sync(0xffffffffu, s2, o);
        }
        const float mu   = s * (1.f / DP);
        const float rstd = rsqrtf(s2 * (1.f / DP) - mu * mu + EPS);
        float xv[4] = {v.x, v.y, v.z, v.w};
        float acc[8] = {};
        #pragma unroll
        for (int c = 0; c < 4; c++) {
            const int d = lane * 4 + c;
            const float y = (xv[c] - mu) * rstd * g[d] + b[d];
            const float* wr = Wb + d * NH;
            #pragma unroll
            for (int hh = 0; hh < 8; hh++) acc[hh] = fmaf(y, wr[hh], acc[hh]);
        }
        #pragma unroll
        for (int hh = 0; hh < 8; hh++) {
            float a = acc[hh];
            #pragma unroll
            for (int o = 16; o; o >>= 1) a += __shfl_xor_sync(0xffffffffu, a, o);
            if (lane == hh) bias_s[j][hh] = a;
        }
    }
    __syncthreads();

    const int h = w;
    const size_t base = ((size_t)h * LRES + i) * LRES;
    float x[12];
    #pragma unroll
    for (int r = 0; r < 6; r++) {
        const int j = 2 * lane + 64 * r;
        float2 lg = *(const float2*)(logits + base + j);
        x[2*r]   = lg.x + bias_s[j][h];
        x[2*r+1] = lg.y + bias_s[j + 1][h];
    }
    float mx = x[0];
    #pragma unroll
    for (int r = 1; r < 12; r++) mx = fmaxf(mx, x[r]);
    #pragma unroll
    for (int o = 16; o; o >>= 1) mx = fmaxf(mx, __shfl_xor_sync(0xffffffffu, mx, o));
    float e[12], sum = 0.f;
    #pragma unroll
    for (int r = 0; r < 12; r++) { e[r] = expf(x[r] - mx); sum += e[r]; }
    #pragma unroll
    for (int o = 16; o; o >>= 1) sum += __shfl_xor_sync(0xffffffffu, sum, o);
    const float inv = 1.f / sum;
    #pragma unroll
    for (int r = 0; r < 6; r++) {
        *(uint32_t*)(attn + base + 2 * lane + 64 * r) =
            f2h2(e[2*r] * inv, e[2*r+1] * inv);
    }
}

// =========================================================================
// T3: aog = fp16(gate * (attn @ vT^T)). Block 128(i) x 64(nd), BK=32(j).
// grid (3, 128, 8). ldmatrix fragments.
// =========================================================================
#define AO_LOAD(stg, j0) do {                                                       \
    _Pragma("unroll")                                                               \
    for (int s_ = 0; s_ < 2; s_++) {                                                \
        const int r_ = (tid >> 2) + 64 * s_;                                        \
        const int c_ = (tid & 3) * 8;                                               \
        cp16(&As[stg][r_][c_], Ah + (size_t)(i0 + r_) * LRES + (j0) + c_);          \
    }                                                                               \
    {                                                                               \
        const int rB_ = tid >> 2;        /* 0..63 = nd */                           \
        const int cB_ = (tid & 3) * 8;                                              \
        const int nB_ = (blockIdx.y << 1) + (rB_ >> 5);                             \
        const int dB_ = rB_ & 31;                                                   \
        cp16(&Bs[stg][rB_][cB_],                                                    \
             vt + ((size_t)((h * NSEQ + nB_) * DHD + dB_)) * LRES + (j0) + cB_);    \
    }                                                                               \
    CP_COMMIT();                                                                    \
} while (0)

__global__ void __launch_bounds__(256, 2) attnout_tc_kernel(
    const __half* __restrict__ attn, const __half* __restrict__ vt,
    const float* __restrict__ gate, __half* __restrict__ aog)
{
    __shared__ __half As[3][128][40];
    __shared__ __half Bs[3][64][40];
    const int tid = threadIdx.x;
    const int i0 = blockIdx.x * 128;
    const int h  = blockIdx.z;
    const int lane = tid & 31, w = tid >> 5;
    const int wm = w >> 1, wn = w & 1;
    const int gid = lane >> 2, tig = lane & 3;
    const int lrow = lane & 7, lgrp = lane >> 3;
    const int arow = wm * 32 + lrow + ((lgrp & 1) ? 8 : 0);
    const int acol = (lgrp & 2) ? 8 : 0;
    const int brow = wn * 32 + lrow + ((lgrp >> 1) ? 8 : 0);
    const int bcol = (lgrp & 1) ? 8 : 0;
    const __half* Ah = attn + (size_t)h * LRES * LRES;
    float acc[2][4][4] = {};

    const int T = LRES / 32;  // 12
    AO_LOAD(0, 0);
    AO_LOAD(1, 32);
    int st = 0, ld = 2;
    for (int t = 0; t < T; t++) {
        if (t + 1 < T) { CP_WAIT(1); } else { CP_WAIT(0); }
        __syncthreads();
        if (t + 2 < T) {
            AO_LOAD(ld, (t + 2) * 32);
            ld = (ld == 2) ? 0 : ld + 1;
        }
        #pragma unroll
        for (int ks = 0; ks < 2; ks++) {
            const int kb = ks * 16;
            uint32_t a[2][4], bfr[4][2];
            #pragma unroll
            for (int mt = 0; mt < 2; mt++)
                ldsm_x4(a[mt][0], a[mt][1], a[mt][2], a[mt][3],
                        &As[st][arow + mt * 16][kb + acol]);
            #pragma unroll
            for (int p = 0; p < 2; p++)
                ldsm_x4(bfr[2*p][0], bfr[2*p][1], bfr[2*p+1][0], bfr[2*p+1][1],
                        &Bs[st][brow + p * 16][kb + bcol]);
            #pragma unroll
            for (int mt = 0; mt < 2; mt++)
                #pragma unroll
                for (int nt = 0; nt < 4; nt++)
                    mma_f16(acc[mt][nt], a[mt][0], a[mt][1], a[mt][2], a[mt][3],
                            bfr[nt][0], bfr[nt][1]);
        }
        st = (st == 2) ? 0 : st + 1;
    }
    #pragma unroll
    for (int mt = 0; mt < 2; mt++) {
        const int r0 = i0 + wm * 32 + mt * 16 + gid;
        #pragma unroll
        for (int nt = 0; nt < 4; nt++) {
            const int col = wn * 32 + nt * 8 + 2 * tig;      // nd within 64
            const int nOut = (blockIdx.y << 1) + (col >> 5);
            const int d = col & 31;
            const size_t p0 = ((size_t)nOut * LRES + r0) * HD + h * DHD + d;
            const size_t p1 = ((size_t)nOut * LRES + r0 + 8) * HD + h * DHD + d;
            const float2 gA = *(const float2*)(gate + p0);
            const float2 gB = *(const float2*)(gate + p1);
            *(uint32_t*)(aog + p0) = f2h2(acc[mt][nt][0] * gA.x, acc[mt][nt][1] * gA.y);
            *(uint32_t*)(aog + p1) = f2h2(acc[mt][nt][2] * gB.x, acc[mt][nt][3] * gB.y);
        }
    }
}
#undef AO_LOAD

// =========================================================================
// launcher
// =========================================================================
extern "C" void kernel_launch(void* const* d_in, const int* in_sizes, int n_in,
                              void* d_out, int out_size)
{
    const float* msa       = (const float*)d_in[0];
    const float* pair      = (const float*)d_in[1];
    const float* ln_msa_g  = (const float*)d_in[2];
    const float* ln_msa_b  = (const float*)d_in[3];
    const float* ln_pair_g = (const float*)d_in[4];
    const float* ln_pair_b = (const float*)d_in[5];
    const float* Wq_sw     = (const float*)d_in[6];
    const float* bq_sw     = (const float*)d_in[7];
    const float* Wk_sw     = (const float*)d_in[8];
    const float* bk_sw     = (const float*)d_in[9];
    const float* Wq        = (const float*)d_in[10];
    const float* Wk        = (const float*)d_in[11];
    const float* Wv        = (const float*)d_in[12];
    const float* Wb        = (const float*)d_in[13];
    const float* Wg        = (const float*)d_in[14];
    const float* bg        = (const float*)d_in[15];
    const float* Wo        = (const float*)d_in[16];
    const float* bo        = (const float*)d_in[17];
    float* out = (float*)d_out;

    __half *m_, *qw_, *k_, *v_, *vt_, *aog_, *attn_, *wpackT_, *w2T_;
    float *qsw_, *ksw_, *q_, *gate_, *sw_, *logits_;
    cudaGetSymbolAddress((void**)&m_,      g_m);
    cudaGetSymbolAddress((void**)&qsw_,    g_qsw);
    cudaGetSymbolAddress((void**)&ksw_,    g_ksw);
    cudaGetSymbolAddress((void**)&q_,      g_q);
    cudaGetSymbolAddress((void**)&qw_,     g_qw);
    cudaGetSymbolAddress((void**)&k_,      g_k);
    cudaGetSymbolAddress((void**)&v_,      g_v);
    cudaGetSymbolAddress((void**)&vt_,     g_vt);
    cudaGetSymbolAddress((void**)&gate_,   g_gate);
    cudaGetSymbolAddress((void**)&aog_,    g_aog);
    cudaGetSymbolAddress((void**)&sw_,     g_sw);
    cudaGetSymbolAddress((void**)&logits_, g_logits);
    cudaGetSymbolAddress((void**)&attn_,   g_attn);
    cudaGetSymbolAddress((void**)&wpackT_, g_wpackT);
    cudaGetSymbolAddress((void**)&w2T_,    g_w2T);

    const float scale = 0.17677669529663687f;  // 1/sqrt(32)
    const __half *WqSWT = w2T_, *WOT = w2T_ + DM * DM;

    const int WG_SMEM = (3 * 128 * 40 * 2) * 2;   // 61440
    const int LG_SMEM = (3 * 64 * 72 * 2) * 2;    // 55296
    cudaFuncSetAttribute((const void*)wgemm_kernel<0>,
        cudaFuncAttributeMaxDynamicSharedMemorySize, WG_SMEM);
    cudaFuncSetAttribute((const void*)wgemm_kernel<1>,
        cudaFuncAttributeMaxDynamicSharedMemorySize, WG_SMEM);
    cudaFuncSetAttribute((const void*)logits_tc_kernel,
        cudaFuncAttributeMaxDynamicSharedMemorySize, LG_SMEM);

    // preprocessing: pack transposed fp16 weights, LN
    cvt_pack_kernel<<<(DM * NWIDE) / 256, 256>>>(Wk_sw, Wq, Wk, Wv, Wg, wpackT_);
    cvt2_kernel<<<dim3(DM * DM / 256, 2), 256>>>(Wq_sw, Wo, w2T_);
    ln_msa_kernel<<<NLROWS / 8, 256>>>(msa, ln_msa_g, ln_msa_b, m_);

    // fused 5-way projection
    wgemm_kernel<0><<<dim3(NWIDE / 128, NLROWS / 128), 256, WG_SMEM>>>(
        m_, wpackT_, NLROWS, DM, NWIDE,
        ksw_, q_, k_, v_, gate_, bk_sw, bg, scale, nullptr);

    // qsw: (m0 @ Wq_sw + bq_sw) * scale
    wgemm_kernel<1><<<dim3(HD / 128, LRES / 128), 256, WG_SMEM>>>(
        m_, WqSWT, LRES, DM, HD,
        nullptr, nullptr, nullptr, nullptr, nullptr, bq_sw, nullptr, scale, qsw_);

    // seq weights + weighted q + v transpose
    seqw_kernel<<<dim3(LRES, NH), 256>>>(qsw_, ksw_, sw_);
    qw_kernel<<<(NLROWS * HD / 4) / 256, 256>>>(q_, sw_, qw_);
    vtrans_kernel<<<dim3(NSEQ, NH), 256>>>(v_, vt_);

    // logits
    logits_tc_kernel<<<dim3(LRES / 64, LRES / 64, NH), 256, LG_SMEM>>>(qw_, k_, logits_);

    // fused pair bias + softmax (fp16 attn)
    pairsoftmax_kernel<<<LRES, 256>>>(pair, ln_pair_g, ln_pair_b, Wb, logits_, attn_);

    // attn @ v (gate fused)
    attnout_tc_kernel<<<dim3(LRES / 128, NSEQ / 2, NH), 256>>>(attn_, vt_, gate_, aog_);

    // final: aog @ Wo + bo
    wgemm_kernel<1><<<dim3(DM / 128, NLROWS / 128), 256, WG_SMEM>>>(
        aog_, WOT, NLROWS, DM, DM,
        nullptr, nullptr, nullptr, nullptr, nullptr, bo, nullptr, 1.f, out);
}

// round 11
// speedup vs baseline: 2.2615x; 1.0044x over previous
#include <cuda_runtime.h>
#include <cuda_fp16.h>
#include <math.h>
#include <stdint.h>

// Problem constants
#define NSEQ 256
#define LRES 384
#define DM   256
#define DP   128
#define NH   8
#define DHD  32
#define HD   256           // NH*DHD
#define NLROWS (NSEQ*LRES) // 98304
#define EPS 1e-5f
#define NWIDE 1280         // 5 fused projection outputs

// -------- scratch (device globals) --------
__device__ __half  g_m[NLROWS * DM];        // LN(msa), fp16
__device__ float   g_qsw[LRES * HD];        // q_sw (scaled), fp32
__device__ float   g_ksw[NLROWS * HD];      // k_sw, fp32
__device__ float   g_q[NLROWS * HD];        // m@Wq, fp32
__device__ __half  g_qw[NLROWS * HD];       // (q * seq_weight), fp16
__device__ __half  g_k[NLROWS * HD];        // m@Wk * scale, fp16
__device__ __half  g_v[NLROWS * HD];        // m@Wv, fp16 [n,j,h,d]
__device__ __half  g_vt[NH * NSEQ * DHD * LRES]; // v^T: [h][n][d][j], fp16
__device__ float   g_gate[NLROWS * HD];     // sigmoid(m@Wg+bg), fp32
__device__ __half  g_aog[NLROWS * HD];      // (attn@v)*gate, fp16
__device__ float   g_sw[NLROWS * NH];       // seq weights
__device__ float   g_logits[NH * LRES * LRES];
__device__ __half  g_attn[NH * LRES * LRES]; // fp16
__device__ __half  g_wpackT[NWIDE * DM];     // packed fp16 [n][k] (K-major!)
__device__ __half  g_w2T[2 * DM * DM];       // fp16 K-major: qSW^T, O^T

// ---- helpers ----
__device__ __forceinline__ uint32_t f2h2(float a, float b) {
    __half2 h = __floats2half2_rn(a, b);
    return *(uint32_t*)&h;
}
__device__ __forceinline__ void mma_f16(float* c,
    uint32_t a0, uint32_t a1, uint32_t a2, uint32_t a3,
    uint32_t b0, uint32_t b1)
{
    asm volatile(
        "mma.sync.aligned.m16n8k16.row.col.f32.f16.f16.f32 "
        "{%0,%1,%2,%3},{%4,%5,%6,%7},{%8,%9},{%0,%1,%2,%3};"
        : "+f"(c[0]), "+f"(c[1]), "+f"(c[2]), "+f"(c[3])
        : "r"(a0), "r"(a1), "r"(a2), "r"(a3), "r"(b0), "r"(b1));
}
__device__ __forceinline__ void cp16(void* s, const void* g) {
    uint32_t sa = (uint32_t)__cvta_generic_to_shared(s);
    asm volatile("cp.async.cg.shared.global [%0], [%1], 16;" :: "r"(sa), "l"(g));
}
__device__ __forceinline__ void ldsm_x4(uint32_t& r0, uint32_t& r1,
                                        uint32_t& r2, uint32_t& r3, const void* p)
{
    uint32_t a = (uint32_t)__cvta_generic_to_shared(p);
    asm volatile("ldmatrix.sync.aligned.m8n8.x4.shared.b16 {%0,%1,%2,%3}, [%4];"
        : "=r"(r0), "=r"(r1), "=r"(r2), "=r"(r3) : "r"(a));
}
#define CP_COMMIT() asm volatile("cp.async.commit_group;")
#define CP_WAIT(n)  asm volatile("cp.async.wait_group %0;" :: "n"(n))

// =========================================================================
// K0a: packed fp16 weight, K-MAJOR: wpackT[c][k], c = [kSW|Q|K|V|G] cols.
// =========================================================================
__global__ void __launch_bounds__(256) cvt_pack_kernel(
    const float* w0, const float* w1, const float* w2, const float* w3,
    const float* w4, __half* dst)
{
    const int idx = blockIdx.x * 256 + threadIdx.x;
    const int c = idx >> 8, k = idx & 255;
    const int seg = c >> 8, cc = c & 255;
    const float* src;
    switch (seg) {
        case 0: src = w0; break; case 1: src = w1; break;
        case 2: src = w2; break; case 3: src = w3; break;
        default: src = w4; break;
    }
    dst[idx] = __float2half(src[k * DM + cc]);
}
__global__ void __launch_bounds__(256) cvt2_kernel(
    const float* w0, const float* w1, __half* dst)
{
    const int m = blockIdx.y;
    const int idx = blockIdx.x * 256 + threadIdx.x;
    const int n = idx >> 8, k = idx & 255;
    const float* src = (m == 0) ? w0 : w1;
    dst[m * (DM * DM) + idx] = __float2half(src[k * DM + n]);
}

// =========================================================================
// K1: LayerNorm, warp-per-row (D=256), 8 rows/block, writes fp16.
// =========================================================================
__global__ void __launch_bounds__(256) ln_msa_kernel(
    const float* __restrict__ x, const float* __restrict__ g,
    const float* __restrict__ b, __half* __restrict__ out)
{
    const int w = threadIdx.x >> 5, lane = threadIdx.x & 31;
    const size_t row = (size_t)blockIdx.x * 8 + w;
    const float* xr = x + row * DM;
    float4 v0 = *(const float4*)(xr + lane * 4);
    float4 v1 = *(const float4*)(xr + 128 + lane * 4);
    float s  = v0.x + v0.y + v0.z + v0.w + v1.x + v1.y + v1.z + v1.w;
    float s2 = v0.x*v0.x + v0.y*v0.y + v0.z*v0.z + v0.w*v0.w
             + v1.x*v1.x + v1.y*v1.y + v1.z*v1.z + v1.w*v1.w;
    #pragma unroll
    for (int o = 16; o; o >>= 1) {
        s  += __shfl_xor_sync(0xffffffffu, s,  o);
        s2 += __shfl_xor_sync(0xffffffffu, s2, o);
    }
    const float mu   = s * (1.f / DM);
    const float rstd = rsqrtf(s2 * (1.f / DM) - mu * mu + EPS);
    float4 g0 = *(const float4*)(g + lane * 4);
    float4 g1 = *(const float4*)(g + 128 + lane * 4);
    float4 b0 = *(const float4*)(b + lane * 4);
    float4 b1 = *(const float4*)(b + 128 + lane * 4);
    uint2 o0, o1;
    o0.x = f2h2((v0.x - mu)*rstd*g0.x + b0.x, (v0.y - mu)*rstd*g0.y + b0.y);
    o0.y = f2h2((v0.z - mu)*rstd*g0.z + b0.z, (v0.w - mu)*rstd*g0.w + b0.w);
    o1.x = f2h2((v1.x - mu)*rstd*g1.x + b1.x, (v1.y - mu)*rstd*g1.y + b1.y);
    o1.y = f2h2((v1.z - mu)*rstd*g1.z + b1.z, (v1.w - mu)*rstd*g1.w + b1.w);
    *(uint2*)(out + row * DM + lane * 4)       = o0;
    *(uint2*)(out + row * DM + 128 + lane * 4) = o1;
}

// =========================================================================
// W1: fp16 GEMM + ldmatrix. Block 128(M) x 64(N), BK=32, 3-stage, 1 sync/iter.
// 8 warps = 4m x 2n of 32x32 tiles. launch_bounds(256,3) -> 24 warps/SM.
// A [M][K] row-major fp16, B [N][K] K-major fp16.
// MODE 0: fused 5-segment projection epilogue. MODE 1: plain fp32 out.
// =========================================================================
#define WG_LOAD(stg, k0) do {                                                 \
    _Pragma("unroll")                                                         \
    for (int s_ = 0; s_ < 2; s_++) {                                          \
        const int r_ = (tid >> 2) + 64 * s_;                                  \
        const int c_ = (tid & 3) * 8;                                         \
        cp16(&As[stg][r_][c_], A + (size_t)(m0 + r_) * K + (k0) + c_);        \
    }                                                                         \
    {                                                                         \
        const int r_ = tid >> 2;                                              \
        const int c_ = (tid & 3) * 8;                                         \
        cp16(&Bs[stg][r_][c_], B + (size_t)(n0 + r_) * K + (k0) + c_);        \
    }                                                                         \
    CP_COMMIT();                                                              \
} while (0)

template<int MODE>
__global__ void __launch_bounds__(256, 3) wgemm_kernel(
    const __half* __restrict__ A, const __half* __restrict__ B,
    int M, int K, int Nld,
    float* __restrict__ ksw, float* __restrict__ qf,
    __half* __restrict__ ktf, __half* __restrict__ vtf,
    float* __restrict__ gatef,
    const float* __restrict__ bias0, const float* __restrict__ bias1,
    float scaleArg, float* __restrict__ C)
{
    __shared__ __half As[3][128][40];
    __shared__ __half Bs[3][64][40];
    const int tid = threadIdx.x;
    const int n0 = blockIdx.x * 64;
    const int m0 = blockIdx.y * 128;
    const int lane = tid & 31, w = tid >> 5;
    const int wm = w >> 1, wn = w & 1;
    const int gid = lane >> 2, tig = lane & 3;
    const int lrow = lane & 7, lgrp = lane >> 3;
    const int arow = wm * 32 + lrow + ((lgrp & 1) ? 8 : 0);
    const int acol = (lgrp & 2) ? 8 : 0;
    const int brow = wn * 32 + lrow + ((lgrp >> 1) ? 8 : 0);
    const int bcol = (lgrp & 1) ? 8 : 0;
    float acc[2][4][4] = {};

    const int T = K >> 5;   // BK=32 -> 8 iters
    WG_LOAD(0, 0);
    WG_LOAD(1, 32);
    int st = 0, ld = 2;
    for (int t = 0; t < T; t++) {
        if (t + 1 < T) { CP_WAIT(1); } else { CP_WAIT(0); }
        __syncthreads();
        if (t + 2 < T) {
            WG_LOAD(ld, (t + 2) << 5);
            ld = (ld == 2) ? 0 : ld + 1;
        }
        #pragma unroll
        for (int ks = 0; ks < 2; ks++) {
            const int kb = ks * 16;
            uint32_t a[2][4], bfr[4][2];
            #pragma unroll
            for (int mt = 0; mt < 2; mt++)
                ldsm_x4(a[mt][0], a[mt][1], a[mt][2], a[mt][3],
                        &As[st][arow + mt * 16][kb + acol]);
            #pragma unroll
            for (int p = 0; p < 2; p++)
                ldsm_x4(bfr[2*p][0], bfr[2*p][1], bfr[2*p+1][0], bfr[2*p+1][1],
                        &Bs[st][brow + p * 16][kb + bcol]);
            #pragma unroll
            for (int mt = 0; mt < 2; mt++)
                #pragma unroll
                for (int nt = 0; nt < 4; nt++)
                    mma_f16(acc[mt][nt], a[mt][0], a[mt][1], a[mt][2], a[mt][3],
                            bfr[nt][0], bfr[nt][1]);
        }
        st = (st == 2) ? 0 : st + 1;
    }
    // epilogue
    const int seg = (MODE == 0) ? (blockIdx.x >> 2) : 0;
    #pragma unroll
    for (int mt = 0; mt < 2; mt++) {
        const int r0 = m0 + wm * 32 + mt * 16 + gid;
        #pragma unroll
        for (int nt = 0; nt < 4; nt++) {
            const int col = n0 + wn * 32 + nt * 8 + 2 * tig;
            float v00 = acc[mt][nt][0], v01 = acc[mt][nt][1];
            float v10 = acc[mt][nt][2], v11 = acc[mt][nt][3];
            if (MODE == 0) {
                const int cc = col & 255;
                const size_t p0 = (size_t)r0 * HD + cc;
                const size_t p1 = (size_t)(r0 + 8) * HD + cc;
                switch (seg) {
                    case 0: {
                        const float b0 = bias0[cc], b1 = bias0[cc + 1];
                        *(float2*)(ksw + p0) = make_float2(v00 + b0, v01 + b1);
                        *(float2*)(ksw + p1) = make_float2(v10 + b0, v11 + b1);
                        break;
                    }
                    case 1: {
                        *(float2*)(qf + p0) = make_float2(v00, v01);
                        *(float2*)(qf + p1) = make_float2(v10, v11);
                        break;
                    }
                    case 2: {
                        *(uint32_t*)(ktf + p0) = f2h2(v00 * scaleArg, v01 * scaleArg);
                        *(uint32_t*)(ktf + p1) = f2h2(v10 * scaleArg, v11 * scaleArg);
                        break;
                    }
                    case 3: {
                        *(uint32_t*)(vtf + p0) = f2h2(v00, v01);
                        *(uint32_t*)(vtf + p1) = f2h2(v10, v11);
                        break;
                    }
                    default: {
                        const float b0 = bias1[cc], b1 = bias1[cc + 1];
                        *(float2*)(gatef + p0) = make_float2(1.f/(1.f+expf(-(v00+b0))),
                                                             1.f/(1.f+expf(-(v01+b1))));
                        *(float2*)(gatef + p1) = make_float2(1.f/(1.f+expf(-(v10+b0))),
                                                             1.f/(1.f+expf(-(v11+b1))));
                        break;
                    }
                }
            } else {
                const float b0 = bias0 ? bias0[col] : 0.f;
                const float b1 = bias0 ? bias0[col + 1] : 0.f;
                *(float2*)(C + (size_t)r0 * Nld + col) =
                    make_float2((v00 + b0) * scaleArg, (v01 + b1) * scaleArg);
                *(float2*)(C + (size_t)(r0 + 8) * Nld + col) =
                    make_float2((v10 + b0) * scaleArg, (v11 + b1) * scaleArg);
            }
        }
    }
}
#undef WG_LOAD

// =========================================================================
// K3: seq-weight softmax over n. grid (L, H).
// =========================================================================
__global__ void __launch_bounds__(256) seqw_kernel(
    const float* __restrict__ qsw, const float* __restrict__ ksw,
    float* __restrict__ sw)
{
    const int i = blockIdx.x, h = blockIdx.y;
    const int t = threadIdx.x;            // = n
    __shared__ __align__(16) float qs[DHD];
    __shared__ float red[8];
    if (t < DHD) qs[t] = qsw[(size_t)i * HD + h * DHD + t];
    __syncthreads();
    const float* kp = ksw + ((size_t)t * LRES + i) * HD + h * DHD;
    float dot = 0.f;
    #pragma unroll
    for (int c = 0; c < 8; c++) {
        float4 k4 = *(const float4*)(kp + 4 * c);
        float4 q4 = *(const float4*)(qs + 4 * c);
        dot += k4.x * q4.x + k4.y * q4.y + k4.z * q4.z + k4.w * q4.w;
    }
    const int w = t >> 5, lane = t & 31;
    float mx = dot;
    #pragma unroll
    for (int o = 16; o; o >>= 1) mx = fmaxf(mx, __shfl_xor_sync(0xffffffffu, mx, o));
    if (!lane) red[w] = mx;
    __syncthreads();
    mx = red[0];
    #pragma unroll
    for (int x = 1; x < 8; x++) mx = fmaxf(mx, red[x]);
    const float e = expf(dot - mx);
    float s = e;
    #pragma unroll
    for (int o = 16; o; o >>= 1) s += __shfl_xor_sync(0xffffffffu, s, o);
    __syncthreads();
    if (!lane) red[w] = s;
    __syncthreads();
    float S = 0.f;
    #pragma unroll
    for (int x = 0; x < 8; x++) S += red[x];
    sw[((size_t)t * LRES + i) * NH + h] = e / S;
}

// =========================================================================
// K3b: qw = fp16(q * seq_weight) elementwise.
// =========================================================================
__global__ void __launch_bounds__(256) qw_kernel(
    const float* __restrict__ q, const float* __restrict__ sw,
    __half* __restrict__ qw)
{
    const size_t i4 = (size_t)blockIdx.x * 256 + threadIdx.x;
    const size_t row = i4 >> 6;
    const int h = (int)((i4 >> 3) & 7);
    const float s = sw[row * NH + h];
    float4 v = *(const float4*)(q + i4 * 4);
    uint2 o;
    o.x = f2h2(v.x * s, v.y * s);
    o.y = f2h2(v.z * s, v.w * s);
    *(uint2*)(qw + i4 * 4) = o;
}

// =========================================================================
// K4b: transpose v -> vT[h][n][d][j] fp16. grid (NSEQ, NH), 256 thr.
// =========================================================================
__global__ void __launch_bounds__(256) vtrans_kernel(
    const __half* __restrict__ v, __half* __restrict__ vt)
{
    __shared__ __half tile[DHD][LRES + 8];
    const int n = blockIdx.x, h = blockIdx.y;
    const int tid = threadIdx.x;
    #pragma unroll
    for (int it = 0; it < 6; it++) {
        const int idx = tid + 256 * it;      // 0..1535
        const int j = idx >> 2;
        const int c = (idx & 3) * 8;         // d-chunk
        uint4 val = *(const uint4*)(v + ((size_t)n * LRES + j) * HD + h * DHD + c);
        const __half* hv = (const __half*)&val;
        #pragma unroll
        for (int x = 0; x < 8; x++) tile[c + x][j] = hv[x];
    }
    __syncthreads();
    #pragma unroll
    for (int it = 0; it < 6; it++) {
        const int idx = tid + 256 * it;      // 0..1535
        const int d = idx / 48;
        const int c = (idx % 48) * 8;        // j-chunk
        uint4 val = *(const uint4*)&tile[d][c];
        *(uint4*)(vt + ((size_t)((h * NSEQ + n) * DHD + d)) * LRES + c) = val;
    }
}

// =========================================================================
// T2: logits (fp16 mma + ldmatrix). Block 64x64, BK=64 halves, 3-stage.
// grid (6,6,8).
// =========================================================================
#define LG_LOAD(stg, np) do {                                                      \
    const int nb_ = (np) * 2;                                                      \
    _Pragma("unroll")                                                              \
    for (int s_ = 0; s_ < 2; s_++) {                                               \
        const int r_ = (tid >> 3) + 32 * s_;                                       \
        const int col_ = (tid & 7) * 8;                                            \
        const int n_ = nb_ + (col_ >> 5);                                          \
        const int d_ = col_ & 31;                                                  \
        cp16(&As[stg][r_][col_], qw + ((size_t)n_ * LRES + i0 + r_) * HD + h * DHD + d_); \
        cp16(&Bs[stg][r_][col_], kk + ((size_t)n_ * LRES + j0 + r_) * HD + h * DHD + d_); \
    }                                                                              \
    CP_COMMIT();                                                                   \
} while (0)

__global__ void __launch_bounds__(256, 2) logits_tc_kernel(
    const __half* __restrict__ qw, const __half* __restrict__ kk,
    float* __restrict__ out)
{
    extern __shared__ __half dynh[];
    __half (*As)[64][72] = (__half (*)[64][72])dynh;
    __half (*Bs)[64][72] = (__half (*)[64][72])(dynh + 3 * 64 * 72);
    const int tid = threadIdx.x;
    const int i0 = blockIdx.x * 64;
    const int j0 = blockIdx.y * 64;
    const int h  = blockIdx.z;
    const int lane = tid & 31, w = tid >> 5;
    const int wm = w >> 1, wn = w & 1;
    const int gid = lane >> 2, tig = lane & 3;
    const int lrow = lane & 7, lgrp = lane >> 3;
    const int arow = wm * 16 + lrow + ((lgrp & 1) ? 8 : 0);
    const int acol = (lgrp & 2) ? 8 : 0;
    const int brow = wn * 32 + lrow + ((lgrp >> 1) ? 8 : 0);
    const int bcol = (lgrp & 1) ? 8 : 0;
    float acc[4][4] = {};

    const int T = NSEQ / 2;   // 128
    LG_LOAD(0, 0);
    LG_LOAD(1, 1);
    int st = 0, ld = 2;
    for (int t = 0; t < T; t++) {
        if (t + 1 < T) { CP_WAIT(1); } else { CP_WAIT(0); }
        __syncthreads();
        if (t + 2 < T) {
            LG_LOAD(ld, t + 2);
            ld = (ld == 2) ? 0 : ld + 1;
        }
        #pragma unroll
        for (int ks = 0; ks < 4; ks++) {
            const int kb = ks * 16;
            uint32_t a[4], bfr[4][2];
            ldsm_x4(a[0], a[1], a[2], a[3], &As[st][arow][kb + acol]);
            #pragma unroll
            for (int p = 0; p < 2; p++)
                ldsm_x4(bfr[2*p][0], bfr[2*p][1], bfr[2*p+1][0], bfr[2*p+1][1],
                        &Bs[st][brow + p * 16][kb + bcol]);
            #pragma unroll
            for (int nt = 0; nt < 4; nt++)
                mma_f16(acc[nt], a[0], a[1], a[2], a[3], bfr[nt][0], bfr[nt][1]);
        }
        st = (st == 2) ? 0 : st + 1;
    }
    const size_t ob = (size_t)h * LRES * LRES;
    const int r0 = i0 + wm * 16 + gid;
    #pragma unroll
    for (int nt = 0; nt < 4; nt++) {
        const int col = j0 + wn * 32 + nt * 8 + 2 * tig;
        *(float2*)(out + ob + (size_t)r0 * LRES + col)     = make_float2(acc[nt][0], acc[nt][1]);
        *(float2*)(out + ob + (size_t)(r0+8) * LRES + col) = make_float2(acc[nt][2], acc[nt][3]);
    }
}
#undef LG_LOAD

// =========================================================================
// K6: fused pair-bias + softmax -> fp16 attn. One block per i (256 thr).
// =========================================================================
__global__ void __launch_bounds__(256) pairsoftmax_kernel(
    const float* __restrict__ pair, const float* __restrict__ g,
    const float* __restrict__ b, const float* __restrict__ Wb,
    const float* __restrict__ logits, __half* __restrict__ attn)
{
    __shared__ float bias_s[LRES][NH + 1];
    const int i = blockIdx.x;
    const int w = threadIdx.x >> 5, lane = threadIdx.x & 31;

    for (int j = w; j < LRES; j += 8) {
        const size_t p = (size_t)i * LRES + j;
        float4 v = *(const float4*)(pair + p * DP + lane * 4);
        float s  = v.x + v.y + v.z + v.w;
        float s2 = v.x*v.x + v.y*v.y + v.z*v.z + v.w*v.w;
        #pragma unroll
        for (int o = 16; o; o >>= 1) {
            s  += __shfl_xor_sync(0xffffffffu, s,  o);
            s2 += __shfl_xor_sync(0xffffffffu, s2, o);
        }
        const float mu   = s * (1.f / DP);
        const float rstd = rsqrtf(s2 * (1.f / DP) - mu * mu + EPS);
        float xv[4] = {v.x, v.y, v.z, v.w};
        float acc[8] = {};
        #pragma unroll
        for (int c = 0; c < 4; c++) {
            const int d = lane * 4 + c;
            const float y = (xv[c] - mu) * rstd * g[d] + b[d];
            const float* wr = Wb + d * NH;
            #pragma unroll
            for (int hh = 0; hh < 8; hh++) acc[hh] = fmaf(y, wr[hh], acc[hh]);
        }
        #pragma unroll
        for (int hh = 0; hh < 8; hh++) {
            float a = acc[hh];
            #pragma unroll
            for (int o = 16; o; o >>= 1) a += __shfl_xor_sync(0xffffffffu, a, o);
            if (lane == hh) bias_s[j][hh] = a;
        }
    }
    __syncthreads();

    const int h = w;
    const size_t base = ((size_t)h * LRES + i) * LRES;
    float x[12];
    #pragma unroll
    for (int r = 0; r < 6; r++) {
        const int j = 2 * lane + 64 * r;
        float2 lg = *(const float2*)(logits + base + j);
        x[2*r]   = lg.x + bias_s[j][h];
        x[2*r+1] = lg.y + bias_s[j + 1][h];
    }
    float mx = x[0];
    #pragma unroll
    for (int r = 1; r < 12; r++) mx = fmaxf(mx, x[r]);
    #pragma unroll
    for (int o = 16; o; o >>= 1) mx = fmaxf(mx, __shfl_xor_sync(0xffffffffu, mx, o));
    float e[12], sum = 0.f;
    #pragma unroll
    for (int r = 0; r < 12; r++) { e[r] = expf(x[r] - mx); sum += e[r]; }
    #pragma unroll
    for (int o = 16; o; o >>= 1) sum += __shfl_xor_sync(0xffffffffu, sum, o);
    const float inv = 1.f / sum;
    #pragma unroll
    for (int r = 0; r < 6; r++) {
        *(uint32_t*)(attn + base + 2 * lane + 64 * r) =
            f2h2(e[2*r] * inv, e[2*r+1] * inv);
    }
}

// =========================================================================
// T3: aog = fp16(gate * (attn @ vT^T)). Block 128(i) x 64(nd), BK=32(j).
// grid (3, 128, 8). ldmatrix fragments.
// =========================================================================
#define AO_LOAD(stg, j0) do {                                                       \
    _Pragma("unroll")                                                               \
    for (int s_ = 0; s_ < 2; s_++) {                                                \
        const int r_ = (tid >> 2) + 64 * s_;                                        \
        const int c_ = (tid & 3) * 8;                                               \
        cp16(&As[stg][r_][c_], Ah + (size_t)(i0 + r_) * LRES + (j0) + c_);          \
    }                                                                               \
    {                                                                               \
        const int rB_ = tid >> 2;        /* 0..63 = nd */                           \
        const int cB_ = (tid & 3) * 8;                                              \
        const int nB_ = (blockIdx.y << 1) + (rB_ >> 5);                             \
        const int dB_ = rB_ & 31;                                                   \
        cp16(&Bs[stg][rB_][cB_],                                                    \
             vt + ((size_t)((h * NSEQ + nB_) * DHD + dB_)) * LRES + (j0) + cB_);    \
    }                                                                               \
    CP_COMMIT();                                                                    \
} while (0)

__global__ void __launch_bounds__(256, 2) attnout_tc_kernel(
    const __half* __restrict__ attn, const __half* __restrict__ vt,
    const float* __restrict__ gate, __half* __restrict__ aog)
{
    __shared__ __half As[3][128][40];
    __shared__ __half Bs[3][64][40];
    const int tid = threadIdx.x;
    const int i0 = blockIdx.x * 128;
    const int h  = blockIdx.z;
    const int lane = tid & 31, w = tid >> 5;
    const int wm = w >> 1, wn = w & 1;
    const int gid = lane >> 2, tig = lane & 3;
    const int lrow = lane & 7, lgrp = lane >> 3;
    const int arow = wm * 32 + lrow + ((lgrp & 1) ? 8 : 0);
    const int acol = (lgrp & 2) ? 8 : 0;
    const int brow = wn * 32 + lrow + ((lgrp >> 1) ? 8 : 0);
    const int bcol = (lgrp & 1) ? 8 : 0;
    const __half* Ah = attn + (size_t)h * LRES * LRES;
    float acc[2][4][4] = {};

    const int T = LRES / 32;  // 12
    AO_LOAD(0, 0);
    AO_LOAD(1, 32);
    int st = 0, ld = 2;
    for (int t = 0; t < T; t++) {
        if (t + 1 < T) { CP_WAIT(1); } else { CP_WAIT(0); }
        __syncthreads();
        if (t + 2 < T) {
            AO_LOAD(ld, (t + 2) * 32);
            ld = (ld == 2) ? 0 : ld + 1;
        }
        #pragma unroll
        for (int ks = 0; ks < 2; ks++) {
            const int kb = ks * 16;
            uint32_t a[2][4], bfr[4][2];
            #pragma unroll
            for (int mt = 0; mt < 2; mt++)
                ldsm_x4(a[mt][0], a[mt][1], a[mt][2], a[mt][3],
                        &As[st][arow + mt * 16][kb + acol]);
            #pragma unroll
            for (int p = 0; p < 2; p++)
                ldsm_x4(bfr[2*p][0], bfr[2*p][1], bfr[2*p+1][0], bfr[2*p+1][1],
                        &Bs[st][brow + p * 16][kb + bcol]);
            #pragma unroll
            for (int mt = 0; mt < 2; mt++)
                #pragma unroll
                for (int nt = 0; nt < 4; nt++)
                    mma_f16(acc[mt][nt], a[mt][0], a[mt][1], a[mt][2], a[mt][3],
                            bfr[nt][0], bfr[nt][1]);
        }
        st = (st == 2) ? 0 : st + 1;
    }
    #pragma unroll
    for (int mt = 0; mt < 2; mt++) {
        const int r0 = i0 + wm * 32 + mt * 16 + gid;
        #pragma unroll
        for (int nt = 0; nt < 4; nt++) {
            const int col = wn * 32 + nt * 8 + 2 * tig;      // nd within 64
            const int nOut = (blockIdx.y << 1) + (col >> 5);
            const int d = col & 31;
            const size_t p0 = ((size_t)nOut * LRES + r0) * HD + h * DHD + d;
            const size_t p1 = ((size_t)nOut * LRES + r0 + 8) * HD + h * DHD + d;
            const float2 gA = *(const float2*)(gate + p0);
            const float2 gB = *(const float2*)(gate + p1);
            *(uint32_t*)(aog + p0) = f2h2(acc[mt][nt][0] * gA.x, acc[mt][nt][1] * gA.y);
            *(uint32_t*)(aog + p1) = f2h2(acc[mt][nt][2] * gB.x, acc[mt][nt][3] * gB.y);
        }
    }
}
#undef AO_LOAD

// =========================================================================
// launcher
// =========================================================================
extern "C" void kernel_launch(void* const* d_in, const int* in_sizes, int n_in,
                              void* d_out, int out_size)
{
    const float* msa       = (const float*)d_in[0];
    const float* pair      = (const float*)d_in[1];
    const float* ln_msa_g  = (const float*)d_in[2];
    const float* ln_msa_b  = (const float*)d_in[3];
    const float* ln_pair_g = (const float*)d_in[4];
    const float* ln_pair_b = (const float*)d_in[5];
    const float* Wq_sw     = (const float*)d_in[6];
    const float* bq_sw     = (const float*)d_in[7];
    const float* Wk_sw     = (const float*)d_in[8];
    const float* bk_sw     = (const float*)d_in[9];
    const float* Wq        = (const float*)d_in[10];
    const float* Wk        = (const float*)d_in[11];
    const float* Wv        = (const float*)d_in[12];
    const float* Wb        = (const float*)d_in[13];
    const float* Wg        = (const float*)d_in[14];
    const float* bg        = (const float*)d_in[15];
    const float* Wo        = (const float*)d_in[16];
    const float* bo        = (const float*)d_in[17];
    float* out = (float*)d_out;

    __half *m_, *qw_, *k_, *v_, *vt_, *aog_, *attn_, *wpackT_, *w2T_;
    float *qsw_, *ksw_, *q_, *gate_, *sw_, *logits_;
    cudaGetSymbolAddress((void**)&m_,      g_m);
    cudaGetSymbolAddress((void**)&qsw_,    g_qsw);
    cudaGetSymbolAddress((void**)&ksw_,    g_ksw);
    cudaGetSymbolAddress((void**)&q_,      g_q);
    cudaGetSymbolAddress((void**)&qw_,     g_qw);
    cudaGetSymbolAddress((void**)&k_,      g_k);
    cudaGetSymbolAddress((void**)&v_,      g_v);
    cudaGetSymbolAddress((void**)&vt_,     g_vt);
    cudaGetSymbolAddress((void**)&gate_,   g_gate);
    cudaGetSymbolAddress((void**)&aog_,    g_aog);
    cudaGetSymbolAddress((void**)&sw_,     g_sw);
    cudaGetSymbolAddress((void**)&logits_, g_logits);
    cudaGetSymbolAddress((void**)&attn_,   g_attn);
    cudaGetSymbolAddress((void**)&wpackT_, g_wpackT);
    cudaGetSymbolAddress((void**)&w2T_,    g_w2T);

    const float scale = 0.17677669529663687f;  // 1/sqrt(32)
    const __half *WqSWT = w2T_, *WOT = w2T_ + DM * DM;

    const int LG_SMEM = (3 * 64 * 72 * 2) * 2;    // 55296
    cudaFuncSetAttribute((const void*)logits_tc_kernel,
        cudaFuncAttributeMaxDynamicSharedMemorySize, LG_SMEM);

    // preprocessing: pack transposed fp16 weights, LN
    cvt_pack_kernel<<<(DM * NWIDE) / 256, 256>>>(Wk_sw, Wq, Wk, Wv, Wg, wpackT_);
    cvt2_kernel<<<dim3(DM * DM / 256, 2), 256>>>(Wq_sw, Wo, w2T_);
    ln_msa_kernel<<<NLROWS / 8, 256>>>(msa, ln_msa_g, ln_msa_b, m_);

    // fused 5-way projection (BN=64 tiles, 3 CTAs/SM)
    wgemm_kernel<0><<<dim3(NWIDE / 64, NLROWS / 128), 256>>>(
        m_, wpackT_, NLROWS, DM, NWIDE,
        ksw_, q_, k_, v_, gate_, bk_sw, bg, scale, nullptr);

    // qsw: (m0 @ Wq_sw + bq_sw) * scale
    wgemm_kernel<1><<<dim3(HD / 64, LRES / 128), 256>>>(
        m_, WqSWT, LRES, DM, HD,
        nullptr, nullptr, nullptr, nullptr, nullptr, bq_sw, nullptr, scale, qsw_);

    // seq weights + weighted q + v transpose
    seqw_kernel<<<dim3(LRES, NH), 256>>>(qsw_, ksw_, sw_);
    qw_kernel<<<(NLROWS * HD / 4) / 256, 256>>>(q_, sw_, qw_);
    vtrans_kernel<<<dim3(NSEQ, NH), 256>>>(v_, vt_);

    // logits
    logits_tc_kernel<<<dim3(LRES / 64, LRES / 64, NH), 256, LG_SMEM>>>(qw_, k_, logits_);

    // fused pair bias + softmax (fp16 attn)
    pairsoftmax_kernel<<<LRES, 256>>>(pair, ln_pair_g, ln_pair_b, Wb, logits_, attn_);

    // attn @ v (gate fused)
    attnout_tc_kernel<<<dim3(LRES / 128, NSEQ / 2, NH), 256>>>(attn_, vt_, gate_, aog_);

    // final: aog @ Wo + bo
    wgemm_kernel<1><<<dim3(DM / 64, NLROWS / 128), 256>>>(
        aog_, WOT, NLROWS, DM, DM,
        nullptr, nullptr, nullptr, nullptr, nullptr, bo, nullptr, 1.f, out);
}